// round 13
// baseline (speedup 1.0000x reference)
#include <cuda_runtime.h>
#include <cstdint>

#define NEG_INF_F (-1e9f)
#define HTHRESH_F (-1e8f)

// B=8, S=512, D=1024, H=16, DK=64
#define BB 8
#define SS 512
#define DD 1024
#define HH 16
#define DK 64
#define MTOT (BB*SS)          // 4096
#define BHTOT (BB*HH)         // 128

// -------- scratch (device globals; no cudaMalloc allowed) --------
__device__ float g_q[BB*HH*SS*DK];
__device__ float g_k[BB*HH*SS*DK];
__device__ float g_v[BB*HH*SS*DK];
__device__ float g_ctx[MTOT*DD];
__device__ float g_res[MTOT*DD];
__device__ float g_xr[MTOT*DD];     // tf32-rounded x
// tf32-rounded, TRANSPOSED weights [N][K] (n-major rows for ldmatrix B-frags)
__device__ float g_wqt[DD*DD];
__device__ float g_wkt[DD*DD];
__device__ float g_wvt[DD*DD];
__device__ float g_wot[DD*DD];
// bit-packed masks: 512 cols -> 16 uint32 words per row
__device__ unsigned g_hmp[BHTOT*SS*16];   // 4 MB
__device__ unsigned g_amp[BB*SS*16];      // 256 KB

// -------- helpers --------
__device__ __forceinline__ unsigned f2tf(float f) {
    unsigned u;
    asm("cvt.rna.tf32.f32 %0, %1;" : "=r"(u) : "f"(f));
    return u;
}
__device__ __forceinline__ float tf2f(float f) {
    return __uint_as_float(f2tf(f));
}
__device__ __forceinline__ void mma8(float c[4], const unsigned a[4], unsigned b0, unsigned b1) {
    asm volatile(
        "mma.sync.aligned.m16n8k8.row.col.f32.tf32.tf32.f32 "
        "{%0,%1,%2,%3}, {%4,%5,%6,%7}, {%8,%9}, {%0,%1,%2,%3};\n"
        : "+f"(c[0]), "+f"(c[1]), "+f"(c[2]), "+f"(c[3])
        : "r"(a[0]), "r"(a[1]), "r"(a[2]), "r"(a[3]), "r"(b0), "r"(b1));
}
__device__ __forceinline__ void ldsm4(unsigned r[4], unsigned saddr) {
    asm volatile("ldmatrix.sync.aligned.m8n8.x4.shared.b16 {%0,%1,%2,%3}, [%4];\n"
                 : "=r"(r[0]), "=r"(r[1]), "=r"(r[2]), "=r"(r[3]) : "r"(saddr));
}
__device__ __forceinline__ void cp16(float* smem_dst, const float* gsrc) {
    unsigned d = (unsigned)__cvta_generic_to_shared(smem_dst);
    asm volatile("cp.async.cg.shared.global [%0], [%1], 16;\n" :: "r"(d), "l"(gsrc));
}
__device__ __forceinline__ void cp_commit() {
    asm volatile("cp.async.commit_group;\n");
}
template<int N>
__device__ __forceinline__ void cp_wait() {
    asm volatile("cp.async.wait_group %0;\n" :: "n"(N));
}

// =====================================================================
// Prep kernels
// =====================================================================
__global__ __launch_bounds__(256)
void prep_round_x(const float* __restrict__ x)
{
    float4* dst = (float4*)g_xr;
    const float4* src = (const float4*)x;
    const int n4 = MTOT * DD / 4;
    for (int i = blockIdx.x * blockDim.x + threadIdx.x; i < n4;
         i += gridDim.x * blockDim.x) {
        float4 v = src[i];
        v.x = tf2f(v.x); v.y = tf2f(v.y); v.z = tf2f(v.z); v.w = tf2f(v.w);
        dst[i] = v;
    }
}
__global__ __launch_bounds__(256)
void prep_transpose_w(const float* __restrict__ Wq, const float* __restrict__ Wk,
                      const float* __restrict__ Wv, const float* __restrict__ Wo)
{
    __shared__ float t[32][33];
    const int z = blockIdx.z;
    const float* W = (z == 0) ? Wq : (z == 1 ? Wk : (z == 2 ? Wv : Wo));
    float* WT = (z == 0) ? g_wqt : (z == 1 ? g_wkt : (z == 2 ? g_wvt : g_wot));
    const int k0 = blockIdx.x * 32;
    const int n0 = blockIdx.y * 32;
    const int tx = threadIdx.x & 31, ty = threadIdx.x >> 5;
    #pragma unroll
    for (int j = 0; j < 4; j++) {
        int k = k0 + ty + j * 8;
        t[ty + j * 8][tx] = tf2f(W[(size_t)k * DD + n0 + tx]);
    }
    __syncthreads();
    #pragma unroll
    for (int j = 0; j < 4; j++) {
        int n = n0 + ty + j * 8;
        WT[(size_t)n * DD + k0 + tx] = t[tx][ty + j * 8];
    }
}
__global__ __launch_bounds__(256)
void pack_masks(const int* __restrict__ hm, const int* __restrict__ am)
{
    const int warp = threadIdx.x >> 5, lane = threadIdx.x & 31;
    const int row = blockIdx.x * 8 + warp;
    if (blockIdx.y == 0) {
        const int* src = hm + (size_t)row * SS;
        unsigned* dst = g_hmp + (size_t)row * 16;
        #pragma unroll
        for (int i = 0; i < 16; i++) {
            unsigned w = __ballot_sync(0xffffffffu, src[i * 32 + lane] != 0);
            if (lane == 0) dst[i] = w;
        }
    } else {
        if (row >= BB * SS) return;
        const int* src = am + (size_t)row * SS;
        unsigned* dst = g_amp + (size_t)row * 16;
        #pragma unroll
        for (int i = 0; i < 16; i++) {
            unsigned w = __ballot_sync(0xffffffffu, src[i * 32 + lane] != 0);
            if (lane == 0) dst[i] = w;
        }
    }
}

// =====================================================================
// GEMM: C[4096,1024] = A @ W (+bias [+residual])   (unchanged from R12)
// =====================================================================
#define GBM 128
#define GBN 128
#define GBK 32
#define GST 3
#define TILE_F (GBM * GBK)
#define GEMM_SMEM_BYTES (GST * TILE_F * 2 * 4)   // 98304

template<int MODE>
__global__ __launch_bounds__(256, 2)
void gemm_tf32_kernel(const float* __restrict__ bias0, const float* __restrict__ bias1,
                      const float* __restrict__ bias2,
                      const float* __restrict__ xres)
{
    extern __shared__ float gsm[];
    float* sA = gsm;
    float* sB = gsm + GST * TILE_F;

    const int z = blockIdx.z;
    const float* WT   = (MODE == 1) ? g_wot : ((z == 0) ? g_wqt : (z == 1 ? g_wkt : g_wvt));
    const float* bias = (z == 0) ? bias0 : (z == 1 ? bias1 : bias2);
    const float* A    = (MODE == 0) ? g_xr : g_ctx;
    float* dst = (MODE == 0) ? ((z == 0) ? g_q : (z == 1 ? g_k : g_v)) : g_res;

    const int m0 = blockIdx.x * GBM;
    const int n0 = blockIdx.y * GBN;
    const int tid = threadIdx.x;
    const int warp = tid >> 5, lane = tid & 31, gid = lane >> 2, tig = lane & 3;
    const int wm = warp & 1, wn = warp >> 1;

    const int l7  = lane & 7;
    const int lhA = (lane >> 3) & 1;
    const int khA = lane >> 4;
    const int khB = (lane >> 3) & 1;
    const int nsB = lane >> 4;

    float acc[4][4][4];
    #pragma unroll
    for (int i = 0; i < 4; i++)
        #pragma unroll
        for (int j = 0; j < 4; j++)
            #pragma unroll
            for (int k = 0; k < 4; k++) acc[i][j][k] = 0.f;

    auto load_tile = [&](int st, int kt) {
        float* dA = sA + st * TILE_F;
        float* dB = sB + st * TILE_F;
        #pragma unroll
        for (int j = 0; j < 4; j++) {
            int idx = tid + 256 * j;
            int r = idx >> 3, c = idx & 7;
            cp16(dA + r * 32 + ((c ^ (r & 7)) << 2),
                 A + (size_t)(m0 + r) * DD + kt + (c << 2));
        }
        #pragma unroll
        for (int j = 0; j < 4; j++) {
            int idx = tid + 256 * j;
            int r = idx >> 3, c = idx & 7;
            cp16(dB + r * 32 + ((c ^ (r & 7)) << 2),
                 WT + (size_t)(n0 + r) * DD + kt + (c << 2));
        }
    };

    #pragma unroll
    for (int s = 0; s < GST - 1; s++) { load_tile(s, s * GBK); cp_commit(); }

    const int NIT = DD / GBK;
    for (int it = 0; it < NIT; it++) {
        cp_wait<GST - 2>();
        __syncthreads();
        int nxt = it + GST - 1;
        if (nxt < NIT) load_tile(nxt % GST, nxt * GBK);
        cp_commit();

        const unsigned tAs = (unsigned)__cvta_generic_to_shared(sA + (it % GST) * TILE_F);
        const unsigned tBs = (unsigned)__cvta_generic_to_shared(sB + (it % GST) * TILE_F);
        #pragma unroll
        for (int kk = 0; kk < GBK; kk += 8) {
            const int c0 = kk >> 2;
            unsigned a[4][4];
            #pragma unroll
            for (int mf = 0; mf < 4; mf++) {
                int row = wm * 64 + mf * 16 + lhA * 8 + l7;
                unsigned saddr = tAs + ((row * 32 + (((c0 + khA) ^ l7) << 2)) << 2);
                ldsm4(a[mf], saddr);
            }
            unsigned b[2][4];
            #pragma unroll
            for (int p = 0; p < 2; p++) {
                int row = wn * 32 + p * 16 + nsB * 8 + l7;
                unsigned saddr = tBs + ((row * 32 + (((c0 + khB) ^ l7) << 2)) << 2);
                ldsm4(b[p], saddr);
            }
            #pragma unroll
            for (int p = 0; p < 2; p++)
                #pragma unroll
                for (int h = 0; h < 2; h++) {
                    const int nf = p * 2 + h;
                    #pragma unroll
                    for (int mf = 0; mf < 4; mf++)
                        mma8(acc[mf][nf], a[mf], b[p][2 * h], b[p][2 * h + 1]);
                }
        }
    }

    #pragma unroll
    for (int mf = 0; mf < 4; mf++) {
        #pragma unroll
        for (int rr = 0; rr < 2; rr++) {
            int m = m0 + wm * 64 + mf * 16 + gid + rr * 8;
            #pragma unroll
            for (int nf = 0; nf < 4; nf++) {
                int n = n0 + wn * 32 + nf * 8 + tig * 2;
                float v0 = acc[mf][nf][rr * 2 + 0] + bias[n];
                float v1 = acc[mf][nf][rr * 2 + 1] + bias[n + 1];
                if (MODE == 0) {
                    int bidx = m >> 9, s = m & 511, hh = n >> 6, d = n & 63;
                    *reinterpret_cast<float2*>(
                        &dst[(((size_t)bidx * HH + hh) * SS + s) * DK + d]) =
                        make_float2(tf2f(v0), tf2f(v1));
                } else {
                    v0 += xres[(size_t)m * DD + n];
                    v1 += xres[(size_t)m * DD + n + 1];
                    *reinterpret_cast<float2*>(&dst[(size_t)m * DD + n]) = make_float2(v0, v1);
                }
            }
        }
    }
}

// =====================================================================
// Fused attention, restructured for 2 CTAs/SM:
//   block = (bh, 32-row q-tile); K and V streamed in 64-row chunks
//   through a shared double buffer. Per chunk: scores (full DK
//   reduction) -> blend (chunk-ahead hv ring + smem bitmasks) -> sS.
//   Then softmax (identical order), then P @ V streamed.
// smem: sS 32x516 (66KB) + 2x 64x68 KV (34KB) + Q 32x68 (8.5KB)
//       + packed masks 4KB  = 111KB  => 2 CTAs/SM.
// =====================================================================
#define QT 32
#define CH 64
#define KVST 68
#define SS_STRIDE 516
#define S_FLOATS (QT * SS_STRIDE)          // 16512
#define KV_FLOATS (CH * KVST)              // 4352
#define Q_FLOATS (QT * KVST)               // 2176
#define AMASK_W (QT * 16)                  // 512
#define ATTN_SMEM_BYTES ((S_FLOATS + 2 * KV_FLOATS + Q_FLOATS + 2 * AMASK_W) * 4) // 113664

__global__ __launch_bounds__(256, 2)
void attn_fused_kernel(const float* __restrict__ help_vals,
                       float* __restrict__ attn_out)
{
    extern __shared__ float smem[];
    float* sS  = smem;                        // scores / P
    float* kv0 = smem + S_FLOATS;             // KV double buffer
    float* kv1 = kv0 + KV_FLOATS;
    float* sQ  = kv1 + KV_FLOATS;
    unsigned* sMH = (unsigned*)(sQ + Q_FLOATS);
    unsigned* sMA = sMH + AMASK_W;

    const int bh = blockIdx.x;
    const int b = bh >> 4;
    const int h = bh & 15;
    const int q0 = blockIdx.y * QT;
    const int tid = threadIdx.x;
    const int warp = tid >> 5, lane = tid & 31, gid = lane >> 2, tig = lane & 3;

    const float* ksrc = g_k + (size_t)bh * SS * DK;
    const float* vsrc = g_v + (size_t)bh * SS * DK;
    float* kvbuf[2] = {kv0, kv1};

    auto load_kv = [&](const float* src, int ch, float* buf) {
        #pragma unroll
        for (int j = 0; j < 4; j++) {
            int idx = tid + 256 * j;
            int r = idx >> 4, c = (idx & 15) << 2;
            cp16(buf + r * KVST + c, src + (size_t)(ch * CH + r) * DK + c);
        }
    };

    // ---- initial loads: Q + masks + K chunk0 (group), K chunk1 (group) ----
    {
        const float* qsrc = g_q + ((size_t)bh * SS + q0) * DK;
        #pragma unroll
        for (int j = 0; j < 2; j++) {
            int idx = tid + 256 * j;
            int r = idx >> 4, c = (idx & 15) << 2;
            cp16(sQ + r * KVST + c, qsrc + r * DK + c);
        }
        if (tid < 128) {
            int r = tid >> 2, c = (tid & 3) << 2;
            cp16((float*)(sMH + r * 16 + c),
                 (const float*)(g_hmp + ((size_t)bh * SS + q0 + r) * 16 + c));
        } else {
            int t = tid - 128;
            int r = t >> 2, c = (t & 3) << 2;
            cp16((float*)(sMA + r * 16 + c),
                 (const float*)(g_amp + ((size_t)b * SS + q0 + r) * 16 + c));
        }
        load_kv(ksrc, 0, kv0);
        cp_commit();
        load_kv(ksrc, 1, kv1);
        cp_commit();
    }

    // ---- phase 1: per 64-key chunk: scores + blend -> sS ----
    // warp grid: wq = warp&1 (16 q-rows), wk = warp>>1 (16 keys)
    const int wq = warp & 1;
    const int wk = warp >> 1;
    const float* hvp = help_vals + ((size_t)bh * SS + q0) * SS;

    // hv ring for chunk 0
    float2 hv[4];
    {
        #pragma unroll
        for (int rr = 0; rr < 2; rr++)
            #pragma unroll
            for (int nf = 0; nf < 2; nf++) {
                int lm = wq * 16 + gid + rr * 8;
                int col = wk * 16 + nf * 8 + tig * 2;
                hv[rr * 2 + nf] = __ldcs(reinterpret_cast<const float2*>(
                    hvp + (size_t)lm * SS + col));
            }
    }

    #pragma unroll 1
    for (int ch = 0; ch < 8; ch++) {
        cp_wait<1>();
        __syncthreads();           // chunk ch resident in kvbuf[ch&1]
        const float* sK = kvbuf[ch & 1];

        float acc[2][4];
        #pragma unroll
        for (int i = 0; i < 2; i++)
            #pragma unroll
            for (int k = 0; k < 4; k++) acc[i][k] = 0.f;

        #pragma unroll
        for (int kk = 0; kk < DK; kk += 8) {
            unsigned a[4];
            int rb = wq * 16 + gid;
            a[0] = __float_as_uint(sQ[rb * KVST + kk + tig]);
            a[1] = __float_as_uint(sQ[(rb + 8) * KVST + kk + tig]);
            a[2] = __float_as_uint(sQ[rb * KVST + kk + 4 + tig]);
            a[3] = __float_as_uint(sQ[(rb + 8) * KVST + kk + 4 + tig]);
            #pragma unroll
            for (int nf = 0; nf < 2; nf++) {
                int nb = wk * 16 + nf * 8 + gid;
                unsigned bb0 = __float_as_uint(sK[nb * KVST + kk + tig]);
                unsigned bb1 = __float_as_uint(sK[nb * KVST + kk + 4 + tig]);
                mma8(acc[nf], a, bb0, bb1);
            }
        }
        __syncthreads();           // all warps done reading kvbuf[ch&1]
        // refill: K chunks ch+2, then V chunks 0,1 at the tail
        if (ch + 2 < 8)      load_kv(ksrc, ch + 2, kvbuf[ch & 1]);
        else                 load_kv(vsrc, ch - 6, kvbuf[ch & 1]);
        cp_commit();

        // prefetch hv ring for next chunk
        float2 hvn[4];
        if (ch < 7) {
            #pragma unroll
            for (int rr = 0; rr < 2; rr++)
                #pragma unroll
                for (int nf = 0; nf < 2; nf++) {
                    int lm = wq * 16 + gid + rr * 8;
                    int col = (ch + 1) * CH + wk * 16 + nf * 8 + tig * 2;
                    hvn[rr * 2 + nf] = __ldcs(reinterpret_cast<const float2*>(
                        hvp + (size_t)lm * SS + col));
                }
        }

        // blend chunk ch -> sS
        #pragma unroll
        for (int rr = 0; rr < 2; rr++) {
            #pragma unroll
            for (int nf = 0; nf < 2; nf++) {
                const int lm = wq * 16 + gid + rr * 8;
                const int col = ch * CH + wk * 16 + nf * 8 + tig * 2;
                const float2 h2 = hv[rr * 2 + nf];
                const unsigned wh = sMH[lm * 16 + (col >> 5)];
                const unsigned wa = sMA[lm * 16 + (col >> 5)];
                const int sh = col & 31;
                float s0 = ((wa >> sh) & 1u) ? NEG_INF_F : acc[nf][rr * 2 + 0] * 0.125f;
                float s1 = ((wa >> (sh + 1)) & 1u) ? NEG_INF_F : acc[nf][rr * 2 + 1] * 0.125f;
                if (((wh >> sh) & 1u) && h2.x > HTHRESH_F) s0 = 0.5f * h2.x + 0.5f * s0;
                if (((wh >> (sh + 1)) & 1u) && h2.y > HTHRESH_F) s1 = 0.5f * h2.y + 0.5f * s1;
                sS[lm * SS_STRIDE + col]     = s0;
                sS[lm * SS_STRIDE + col + 1] = s1;
            }
        }
        #pragma unroll
        for (int i = 0; i < 4; i++) hv[i] = hvn[i];
    }
    __syncthreads();   // all scores written

    // ---- phase 2: softmax (4 rows per warp); attn out via __stcs ----
    {
        float* aout = attn_out + ((size_t)bh * SS + q0) * SS;
        #pragma unroll 1
        for (int j = 0; j < 4; j++) {
            int r = warp * 4 + j;
            float* row = &sS[r * SS_STRIDE];
            float vals[16];
            float mx = -3e38f;
            #pragma unroll
            for (int i = 0; i < 16; i++) { vals[i] = row[lane + 32 * i]; mx = fmaxf(mx, vals[i]); }
            #pragma unroll
            for (int o = 16; o > 0; o >>= 1) mx = fmaxf(mx, __shfl_xor_sync(0xffffffffu, mx, o));
            float sum = 0.f;
            #pragma unroll
            for (int i = 0; i < 16; i++) { vals[i] = __expf(vals[i] - mx); sum += vals[i]; }
            #pragma unroll
            for (int o = 16; o > 0; o >>= 1) sum += __shfl_xor_sync(0xffffffffu, sum, o);
            float inv = 1.0f / sum;
            #pragma unroll
            for (int i = 0; i < 16; i++) {
                float p = vals[i] * inv;
                __stcs(&aout[(size_t)r * SS + lane + 32 * i], p);
                row[lane + 32 * i] = tf2f(p);
            }
        }
    }
    __syncthreads();   // P complete

    // ---- phase 3: ctx = P @ V, V streamed (V0,V1 already in flight) ----
    // warp grid: wm = warp&1 (16 rows), wn = warp>>1 (16 d-cols)
    const int wm3 = warp & 1;
    const int wn3 = warp >> 1;
    float cacc[2][4];
    #pragma unroll
    for (int i = 0; i < 2; i++)
        #pragma unroll
        for (int k = 0; k < 4; k++) cacc[i][k] = 0.f;

    #pragma unroll 1
    for (int ch = 0; ch < 8; ch++) {
        cp_wait<1>();
        __syncthreads();           // V chunk ch resident
        const float* sV = kvbuf[ch & 1];

        #pragma unroll
        for (int kk = 0; kk < CH; kk += 8) {
            unsigned a[4];
            int rb = wm3 * 16 + gid;
            int col = ch * CH + kk + tig;
            a[0] = __float_as_uint(sS[rb * SS_STRIDE + col]);
            a[1] = __float_as_uint(sS[(rb + 8) * SS_STRIDE + col]);
            a[2] = __float_as_uint(sS[rb * SS_STRIDE + col + 4]);
            a[3] = __float_as_uint(sS[(rb + 8) * SS_STRIDE + col + 4]);
            #pragma unroll
            for (int nf = 0; nf < 2; nf++) {
                int nb = wn3 * 16 + nf * 8 + gid;
                unsigned bb0 = __float_as_uint(sV[(kk + tig) * KVST + nb]);
                unsigned bb1 = __float_as_uint(sV[(kk + 4 + tig) * KVST + nb]);
                mma8(cacc[nf], a, bb0, bb1);
            }
        }
        __syncthreads();           // done reading kvbuf[ch&1]
        if (ch + 2 < 8) load_kv(vsrc, ch + 2, kvbuf[ch & 1]);
        cp_commit();
    }

    // write tf32-rounded ctx tile -> g_ctx [m = b*S+s][h*64+d]
    #pragma unroll
    for (int rr = 0; rr < 2; rr++) {
        int s = q0 + wm3 * 16 + gid + rr * 8;
        #pragma unroll
        for (int nf = 0; nf < 2; nf++) {
            int d = wn3 * 16 + nf * 8 + tig * 2;
            *reinterpret_cast<float2*>(
                &g_ctx[((size_t)b * SS + s) * DD + h * DK + d]) =
                make_float2(tf2f(cacc[nf][rr * 2]), tf2f(cacc[nf][rr * 2 + 1]));
        }
    }
}

// =====================================================================
// LayerNorm over rows of g_res -> y output (block per row, float4)
// =====================================================================
__global__ __launch_bounds__(256)
void ln_kernel(const float* __restrict__ ln_g, const float* __restrict__ ln_b,
               float* __restrict__ y_out)
{
    __shared__ float rs[8], rq[8];
    const int r = blockIdx.x, t = threadIdx.x;
    const float4* row4 = reinterpret_cast<const float4*>(g_res + (size_t)r * DD);
    float4 v = row4[t];
    float s = v.x + v.y + v.z + v.w;
    float q = v.x * v.x + v.y * v.y + v.z * v.z + v.w * v.w;
    #pragma unroll
    for (int o = 16; o > 0; o >>= 1) {
        s += __shfl_xor_sync(0xffffffffu, s, o);
        q += __shfl_xor_sync(0xffffffffu, q, o);
    }
    if ((t & 31) == 0) { rs[t >> 5] = s; rq[t >> 5] = q; }
    __syncthreads();
    if (t < 32) {
        float ss = (t < 8) ? rs[t] : 0.f;
        float qq = (t < 8) ? rq[t] : 0.f;
        #pragma unroll
        for (int o = 4; o > 0; o >>= 1) {
            ss += __shfl_xor_sync(0xffffffffu, ss, o);
            qq += __shfl_xor_sync(0xffffffffu, qq, o);
        }
        if (t == 0) { rs[0] = ss; rq[0] = qq; }
    }
    __syncthreads();
    float mean = rs[0] * (1.0f / 1024.0f);
    float var  = rq[0] * (1.0f / 1024.0f) - mean * mean;
    float rstd = rsqrtf(var + 1e-5f);
    const float4 g4 = reinterpret_cast<const float4*>(ln_g)[t];
    const float4 b4 = reinterpret_cast<const float4*>(ln_b)[t];
    float4 o;
    o.x = (v.x - mean) * rstd * g4.x + b4.x;
    o.y = (v.y - mean) * rstd * g4.y + b4.y;
    o.z = (v.z - mean) * rstd * g4.z + b4.z;
    o.w = (v.w - mean) * rstd * g4.w + b4.w;
    reinterpret_cast<float4*>(y_out + (size_t)r * DD)[t] = o;
}

// =====================================================================
extern "C" void kernel_launch(void* const* d_in, const int* in_sizes, int n_in,
                              void* d_out, int out_size)
{
    const float* x    = (const float*)d_in[0];
    const float* Wq   = (const float*)d_in[1];
    const float* bq   = (const float*)d_in[2];
    const float* Wk   = (const float*)d_in[3];
    const float* bk   = (const float*)d_in[4];
    const float* Wv   = (const float*)d_in[5];
    const float* bv   = (const float*)d_in[6];
    const float* Wo   = (const float*)d_in[7];
    const float* bo   = (const float*)d_in[8];
    const float* ln_g = (const float*)d_in[9];
    const float* ln_b = (const float*)d_in[10];
    const float* hv   = (const float*)d_in[11];
    const int*   hm   = (const int*)d_in[12];
    const int*   am   = (const int*)d_in[13];

    float* out = (float*)d_out;
    float* y_out    = out;                          // [B,S,D]
    float* attn_out = out + (size_t)MTOT * DD;      // [B,H,S,S]

    cudaFuncSetAttribute(gemm_tf32_kernel<0>,
                         cudaFuncAttributeMaxDynamicSharedMemorySize, GEMM_SMEM_BYTES);
    cudaFuncSetAttribute(gemm_tf32_kernel<1>,
                         cudaFuncAttributeMaxDynamicSharedMemorySize, GEMM_SMEM_BYTES);
    cudaFuncSetAttribute(attn_fused_kernel,
                         cudaFuncAttributeMaxDynamicSharedMemorySize, ATTN_SMEM_BYTES);

    // 0) prep: round x; round+transpose weights; pack masks to bits
    prep_round_x<<<dim3(148), 256>>>(x);
    prep_transpose_w<<<dim3(32, 32, 4), 256>>>(Wq, Wk, Wv, Wo);
    pack_masks<<<dim3(8192, 2), 256>>>(hm, am);
    // 1) QKV projections
    gemm_tf32_kernel<0><<<dim3(32, 8, 3), 256, GEMM_SMEM_BYTES>>>(bq, bk, bv, nullptr);
    // 2) fused attention (2 CTAs/SM, K/V streamed)
    attn_fused_kernel<<<dim3(BHTOT, 16), 256, ATTN_SMEM_BYTES>>>(hv, attn_out);
    // 3) out projection + bias + residual
    gemm_tf32_kernel<1><<<dim3(32, 8, 1), 256, GEMM_SMEM_BYTES>>>(bo, bo, bo, x);
    // 4) LayerNorm -> y
    ln_kernel<<<dim3(MTOT), 256>>>(ln_g, ln_b, y_out);
}

// round 14
// speedup vs baseline: 1.0433x; 1.0433x over previous
#include <cuda_runtime.h>
#include <cstdint>

#define NEG_INF_F (-1e9f)
#define HTHRESH_F (-1e8f)

// B=8, S=512, D=1024, H=16, DK=64
#define BB 8
#define SS 512
#define DD 1024
#define HH 16
#define DK 64
#define MTOT (BB*SS)          // 4096
#define BHTOT (BB*HH)         // 128

// -------- scratch (device globals; no cudaMalloc allowed) --------
__device__ float g_q[BB*HH*SS*DK];
__device__ float g_k[BB*HH*SS*DK];
__device__ float g_v[BB*HH*SS*DK];
__device__ float g_ctx[MTOT*DD];
__device__ float g_res[MTOT*DD];
__device__ float g_xr[MTOT*DD];     // tf32-rounded x
// tf32-rounded, TRANSPOSED weights [N][K] (n-major rows for ldmatrix B-frags)
__device__ float g_wqt[DD*DD];
__device__ float g_wkt[DD*DD];
__device__ float g_wvt[DD*DD];
__device__ float g_wot[DD*DD];
// bit-packed masks: 512 cols -> 16 uint32 words per row
__device__ unsigned g_hmp[BHTOT*SS*16];   // 4 MB
__device__ unsigned g_amp[BB*SS*16];      // 256 KB

// -------- helpers --------
__device__ __forceinline__ unsigned f2tf(float f) {
    unsigned u;
    asm("cvt.rna.tf32.f32 %0, %1;" : "=r"(u) : "f"(f));
    return u;
}
__device__ __forceinline__ float tf2f(float f) {
    return __uint_as_float(f2tf(f));
}
__device__ __forceinline__ void mma8(float c[4], const unsigned a[4], unsigned b0, unsigned b1) {
    asm volatile(
        "mma.sync.aligned.m16n8k8.row.col.f32.tf32.tf32.f32 "
        "{%0,%1,%2,%3}, {%4,%5,%6,%7}, {%8,%9}, {%0,%1,%2,%3};\n"
        : "+f"(c[0]), "+f"(c[1]), "+f"(c[2]), "+f"(c[3])
        : "r"(a[0]), "r"(a[1]), "r"(a[2]), "r"(a[3]), "r"(b0), "r"(b1));
}
__device__ __forceinline__ void ldsm4(unsigned r[4], unsigned saddr) {
    asm volatile("ldmatrix.sync.aligned.m8n8.x4.shared.b16 {%0,%1,%2,%3}, [%4];\n"
                 : "=r"(r[0]), "=r"(r[1]), "=r"(r[2]), "=r"(r[3]) : "r"(saddr));
}
__device__ __forceinline__ void cp16(float* smem_dst, const float* gsrc) {
    unsigned d = (unsigned)__cvta_generic_to_shared(smem_dst);
    asm volatile("cp.async.cg.shared.global [%0], [%1], 16;\n" :: "r"(d), "l"(gsrc));
}
__device__ __forceinline__ void cp_commit() {
    asm volatile("cp.async.commit_group;\n");
}
template<int N>
__device__ __forceinline__ void cp_wait() {
    asm volatile("cp.async.wait_group %0;\n" :: "n"(N));
}

// =====================================================================
// Prep kernels
// =====================================================================
__global__ __launch_bounds__(256)
void prep_round_x(const float* __restrict__ x)
{
    float4* dst = (float4*)g_xr;
    const float4* src = (const float4*)x;
    const int n4 = MTOT * DD / 4;
    for (int i = blockIdx.x * blockDim.x + threadIdx.x; i < n4;
         i += gridDim.x * blockDim.x) {
        float4 v = src[i];
        v.x = tf2f(v.x); v.y = tf2f(v.y); v.z = tf2f(v.z); v.w = tf2f(v.w);
        dst[i] = v;
    }
}
__global__ __launch_bounds__(256)
void prep_transpose_w(const float* __restrict__ Wq, const float* __restrict__ Wk,
                      const float* __restrict__ Wv, const float* __restrict__ Wo)
{
    __shared__ float t[32][33];
    const int z = blockIdx.z;
    const float* W = (z == 0) ? Wq : (z == 1 ? Wk : (z == 2 ? Wv : Wo));
    float* WT = (z == 0) ? g_wqt : (z == 1 ? g_wkt : (z == 2 ? g_wvt : g_wot));
    const int k0 = blockIdx.x * 32;
    const int n0 = blockIdx.y * 32;
    const int tx = threadIdx.x & 31, ty = threadIdx.x >> 5;
    #pragma unroll
    for (int j = 0; j < 4; j++) {
        int k = k0 + ty + j * 8;
        t[ty + j * 8][tx] = tf2f(W[(size_t)k * DD + n0 + tx]);
    }
    __syncthreads();
    #pragma unroll
    for (int j = 0; j < 4; j++) {
        int n = n0 + ty + j * 8;
        WT[(size_t)n * DD + k0 + tx] = t[tx][ty + j * 8];
    }
}
__global__ __launch_bounds__(256)
void pack_masks(const int* __restrict__ hm, const int* __restrict__ am)
{
    const int warp = threadIdx.x >> 5, lane = threadIdx.x & 31;
    const int row = blockIdx.x * 8 + warp;
    if (blockIdx.y == 0) {
        const int* src = hm + (size_t)row * SS;
        unsigned* dst = g_hmp + (size_t)row * 16;
        #pragma unroll
        for (int i = 0; i < 16; i++) {
            unsigned w = __ballot_sync(0xffffffffu, src[i * 32 + lane] != 0);
            if (lane == 0) dst[i] = w;
        }
    } else {
        if (row >= BB * SS) return;
        const int* src = am + (size_t)row * SS;
        unsigned* dst = g_amp + (size_t)row * 16;
        #pragma unroll
        for (int i = 0; i < 16; i++) {
            unsigned w = __ballot_sync(0xffffffffu, src[i * 32 + lane] != 0);
            if (lane == 0) dst[i] = w;
        }
    }
}

// =====================================================================
// GEMM: C[4096,1024] = A @ W (+bias [+residual])   (unchanged from R12)
// =====================================================================
#define GBM 128
#define GBN 128
#define GBK 32
#define GST 3
#define TILE_F (GBM * GBK)
#define GEMM_SMEM_BYTES (GST * TILE_F * 2 * 4)   // 98304

template<int MODE>
__global__ __launch_bounds__(256, 2)
void gemm_tf32_kernel(const float* __restrict__ bias0, const float* __restrict__ bias1,
                      const float* __restrict__ bias2,
                      const float* __restrict__ xres)
{
    extern __shared__ float gsm[];
    float* sA = gsm;
    float* sB = gsm + GST * TILE_F;

    const int z = blockIdx.z;
    const float* WT   = (MODE == 1) ? g_wot : ((z == 0) ? g_wqt : (z == 1 ? g_wkt : g_wvt));
    const float* bias = (z == 0) ? bias0 : (z == 1 ? bias1 : bias2);
    const float* A    = (MODE == 0) ? g_xr : g_ctx;
    float* dst = (MODE == 0) ? ((z == 0) ? g_q : (z == 1 ? g_k : g_v)) : g_res;

    const int m0 = blockIdx.x * GBM;
    const int n0 = blockIdx.y * GBN;
    const int tid = threadIdx.x;
    const int warp = tid >> 5, lane = tid & 31, gid = lane >> 2, tig = lane & 3;
    const int wm = warp & 1, wn = warp >> 1;

    const int l7  = lane & 7;
    const int lhA = (lane >> 3) & 1;
    const int khA = lane >> 4;
    const int khB = (lane >> 3) & 1;
    const int nsB = lane >> 4;

    float acc[4][4][4];
    #pragma unroll
    for (int i = 0; i < 4; i++)
        #pragma unroll
        for (int j = 0; j < 4; j++)
            #pragma unroll
            for (int k = 0; k < 4; k++) acc[i][j][k] = 0.f;

    auto load_tile = [&](int st, int kt) {
        float* dA = sA + st * TILE_F;
        float* dB = sB + st * TILE_F;
        #pragma unroll
        for (int j = 0; j < 4; j++) {
            int idx = tid + 256 * j;
            int r = idx >> 3, c = idx & 7;
            cp16(dA + r * 32 + ((c ^ (r & 7)) << 2),
                 A + (size_t)(m0 + r) * DD + kt + (c << 2));
        }
        #pragma unroll
        for (int j = 0; j < 4; j++) {
            int idx = tid + 256 * j;
            int r = idx >> 3, c = idx & 7;
            cp16(dB + r * 32 + ((c ^ (r & 7)) << 2),
                 WT + (size_t)(n0 + r) * DD + kt + (c << 2));
        }
    };

    #pragma unroll
    for (int s = 0; s < GST - 1; s++) { load_tile(s, s * GBK); cp_commit(); }

    const int NIT = DD / GBK;
    for (int it = 0; it < NIT; it++) {
        cp_wait<GST - 2>();
        __syncthreads();
        int nxt = it + GST - 1;
        if (nxt < NIT) load_tile(nxt % GST, nxt * GBK);
        cp_commit();

        const unsigned tAs = (unsigned)__cvta_generic_to_shared(sA + (it % GST) * TILE_F);
        const unsigned tBs = (unsigned)__cvta_generic_to_shared(sB + (it % GST) * TILE_F);
        #pragma unroll
        for (int kk = 0; kk < GBK; kk += 8) {
            const int c0 = kk >> 2;
            unsigned a[4][4];
            #pragma unroll
            for (int mf = 0; mf < 4; mf++) {
                int row = wm * 64 + mf * 16 + lhA * 8 + l7;
                unsigned saddr = tAs + ((row * 32 + (((c0 + khA) ^ l7) << 2)) << 2);
                ldsm4(a[mf], saddr);
            }
            unsigned b[2][4];
            #pragma unroll
            for (int p = 0; p < 2; p++) {
                int row = wn * 32 + p * 16 + nsB * 8 + l7;
                unsigned saddr = tBs + ((row * 32 + (((c0 + khB) ^ l7) << 2)) << 2);
                ldsm4(b[p], saddr);
            }
            #pragma unroll
            for (int p = 0; p < 2; p++)
                #pragma unroll
                for (int h = 0; h < 2; h++) {
                    const int nf = p * 2 + h;
                    #pragma unroll
                    for (int mf = 0; mf < 4; mf++)
                        mma8(acc[mf][nf], a[mf], b[p][2 * h], b[p][2 * h + 1]);
                }
        }
    }

    #pragma unroll
    for (int mf = 0; mf < 4; mf++) {
        #pragma unroll
        for (int rr = 0; rr < 2; rr++) {
            int m = m0 + wm * 64 + mf * 16 + gid + rr * 8;
            #pragma unroll
            for (int nf = 0; nf < 4; nf++) {
                int n = n0 + wn * 32 + nf * 8 + tig * 2;
                float v0 = acc[mf][nf][rr * 2 + 0] + bias[n];
                float v1 = acc[mf][nf][rr * 2 + 1] + bias[n + 1];
                if (MODE == 0) {
                    int bidx = m >> 9, s = m & 511, hh = n >> 6, d = n & 63;
                    *reinterpret_cast<float2*>(
                        &dst[(((size_t)bidx * HH + hh) * SS + s) * DK + d]) =
                        make_float2(tf2f(v0), tf2f(v1));
                } else {
                    v0 += xres[(size_t)m * DD + n];
                    v1 += xres[(size_t)m * DD + n + 1];
                    *reinterpret_cast<float2*>(&dst[(size_t)m * DD + n]) = make_float2(v0, v1);
                }
            }
        }
    }
}

// =====================================================================
// Fused attention (R12 structure, PF=8 hv ring): block = (b,h, 64-row
// q-tile), 256 threads. Masks bit-packed in smem; hv-only register ring
// pre-issued 8 deep before phase 1.
// =====================================================================
#define AST 72
#define SK_FLOATS (512 * AST)
#define VB_FLOATS (64 * AST)
#define MASK_WORDS (64 * 16)               // per mask: 1024 words = 4KB
#define ATTN_SMEM_BYTES ((SK_FLOATS + 3 * VB_FLOATS + 2 * MASK_WORDS) * 4)  // 210944
#define PF 8

__global__ __launch_bounds__(256)
void attn_fused_kernel(const float* __restrict__ help_vals,
                       float* __restrict__ attn_out)
{
    extern __shared__ float smem[];
    float* sK = smem;
    float* vb0 = smem + SK_FLOATS;
    float* vb1 = vb0 + VB_FLOATS;
    float* vb2 = vb1 + VB_FLOATS;
    unsigned* sMH = (unsigned*)(vb2 + VB_FLOATS);
    unsigned* sMA = sMH + MASK_WORDS;

    const int bh = blockIdx.x;
    const int b = bh >> 4;
    const int h = bh & 15;
    const int q0 = blockIdx.y * 64;
    const int tid = threadIdx.x;
    const int warp = tid >> 5, lane = tid & 31, gid = lane >> 2, tig = lane & 3;

    const float* vsrcb = g_v + (size_t)bh * SS * DK;

    // ---- async load Q tile, full K, and bit-packed masks ----
    {
        const float* qsrc = g_q + ((size_t)bh * SS + q0) * DK;
        #pragma unroll
        for (int j = 0; j < 4; j++) {
            int idx = tid + 256 * j;
            int r = idx >> 4, c = (idx & 15) << 2;
            cp16(vb0 + r * AST + c, qsrc + r * DK + c);
        }
        const float* ksrc = g_k + (size_t)bh * SS * DK;
        #pragma unroll
        for (int j = 0; j < 32; j++) {
            int idx = tid + 256 * j;
            int r = idx >> 4, c = (idx & 15) << 2;
            cp16(sK + r * AST + c, ksrc + r * DK + c);
        }
        {   // masks: 64 rows x 16 words each; 4 cp16 per row
            int r = tid >> 2, c = (tid & 3) << 2;
            cp16((float*)(sMH + r * 16 + c),
                 (const float*)(g_hmp + ((size_t)bh * SS + q0 + r) * 16 + c));
            cp16((float*)(sMA + r * 16 + c),
                 (const float*)(g_amp + ((size_t)b * SS + q0 + r) * 16 + c));
        }
        cp_commit();
        cp_wait<0>();
        __syncthreads();
    }

    const int wm = warp & 1;
    const int wn = warp >> 1;

    // ---- pre-issue first hv batch, 8 deep (overlaps phase-1 mma) ----
    const float* hvp = help_vals + ((size_t)bh * SS + q0) * SS;
    const int base_lm = wm * 32 + gid;
    const int base_ln = wn * 128 + tig * 2;

    float2 hvb[PF];
    #pragma unroll
    for (int i = 0; i < PF; i++) {
        int lm = base_lm + ((i >> 5) << 4) + (((i >> 4) & 1) << 3);
        int ln = base_ln + ((i & 15) << 3);
        hvb[i] = __ldcs(reinterpret_cast<const float2*>(hvp + (size_t)lm * SS + ln));
    }

    // ---- phase 1: scores = Q @ K^T ----
    float acc[2][16][4];
    #pragma unroll
    for (int i = 0; i < 2; i++)
        #pragma unroll
        for (int j = 0; j < 16; j++)
            #pragma unroll
            for (int k = 0; k < 4; k++) acc[i][j][k] = 0.f;

    #pragma unroll 1
    for (int kk = 0; kk < DK; kk += 8) {
        unsigned a[2][4];
        #pragma unroll
        for (int mf = 0; mf < 2; mf++) {
            int rb = wm * 32 + mf * 16 + gid;
            a[mf][0] = __float_as_uint(vb0[rb * AST + kk + tig]);
            a[mf][1] = __float_as_uint(vb0[(rb + 8) * AST + kk + tig]);
            a[mf][2] = __float_as_uint(vb0[rb * AST + kk + 4 + tig]);
            a[mf][3] = __float_as_uint(vb0[(rb + 8) * AST + kk + 4 + tig]);
        }
        #pragma unroll
        for (int nf = 0; nf < 16; nf++) {
            int nb = wn * 128 + nf * 8 + gid;
            unsigned bb0 = __float_as_uint(sK[nb * AST + kk + tig]);
            unsigned bb1 = __float_as_uint(sK[nb * AST + kk + 4 + tig]);
            mma8(acc[0][nf], a[0], bb0, bb1);
            mma8(acc[1][nf], a[1], bb0, bb1);
        }
    }
    __syncthreads();   // K/Q dead; overlay scores on sK

    // prefetch V chunks 0,1 (land during blend + softmax)
    {
        #pragma unroll
        for (int j = 0; j < 4; j++) {
            int idx = tid + 256 * j;
            int r = idx >> 4, c = (idx & 15) << 2;
            cp16(vb1 + r * AST + c, vsrcb + r * DK + c);
        }
        cp_commit();
        #pragma unroll
        for (int j = 0; j < 4; j++) {
            int idx = tid + 256 * j;
            int r = idx >> 4, c = (idx & 15) << 2;
            cp16(vb2 + r * AST + c, vsrcb + (64 + r) * DK + c);
        }
        cp_commit();
    }

    // ---- blend: scale + attn_mask + dependency blend -> sK ----
    {
        #pragma unroll
        for (int i = 0; i < 64; i++) {
            const int slot = i & (PF - 1);
            float2 hv2 = hvb[slot];
            if (i + PF < 64) {
                int j = i + PF;
                int lmp = base_lm + ((j >> 5) << 4) + (((j >> 4) & 1) << 3);
                int lnp = base_ln + ((j & 15) << 3);
                hvb[slot] = __ldcs(reinterpret_cast<const float2*>(
                    hvp + (size_t)lmp * SS + lnp));
            }
            const int mf = i >> 5, rr = (i >> 4) & 1, nf = i & 15;
            const int lm = base_lm + (mf << 4) + (rr << 3);
            const int ln = base_ln + (nf << 3);
            const unsigned wh = sMH[lm * 16 + (ln >> 5)];
            const unsigned wa = sMA[lm * 16 + (ln >> 5)];
            const int sh = ln & 31;
            float s0 = ((wa >> sh) & 1u) ? NEG_INF_F : acc[mf][nf][rr * 2 + 0] * 0.125f;
            float s1 = ((wa >> (sh + 1)) & 1u) ? NEG_INF_F : acc[mf][nf][rr * 2 + 1] * 0.125f;
            if (((wh >> sh) & 1u) && hv2.x > HTHRESH_F) s0 = 0.5f * hv2.x + 0.5f * s0;
            if (((wh >> (sh + 1)) & 1u) && hv2.y > HTHRESH_F) s1 = 0.5f * hv2.y + 0.5f * s1;
            sK[lm * 516 + ln]     = s0;
            sK[lm * 516 + ln + 1] = s1;
        }
    }
    __syncthreads();

    // ---- phase 2: softmax per row; write attn (__stcs); keep tf32 P ----
    {
        float* aout = attn_out + ((size_t)bh * SS + q0) * SS;
        #pragma unroll 1
        for (int j = 0; j < 8; j++) {
            int r = warp * 8 + j;
            float* row = &sK[r * 516];
            float vals[16];
            float mx = -3e38f;
            #pragma unroll
            for (int i = 0; i < 16; i++) { vals[i] = row[lane + 32 * i]; mx = fmaxf(mx, vals[i]); }
            #pragma unroll
            for (int o = 16; o > 0; o >>= 1) mx = fmaxf(mx, __shfl_xor_sync(0xffffffffu, mx, o));
            float sum = 0.f;
            #pragma unroll
            for (int i = 0; i < 16; i++) { vals[i] = __expf(vals[i] - mx); sum += vals[i]; }
            #pragma unroll
            for (int o = 16; o > 0; o >>= 1) sum += __shfl_xor_sync(0xffffffffu, sum, o);
            float inv = 1.0f / sum;
            #pragma unroll
            for (int i = 0; i < 16; i++) {
                float p = vals[i] * inv;
                __stcs(&aout[(size_t)r * SS + lane + 32 * i], p);
                row[lane + 32 * i] = tf2f(p);
            }
        }
    }

    // ---- phase 3: ctx = P @ V, triple-buffered V chunks ----
    const int wm3 = warp & 3;
    const int wn3 = warp >> 2;
    float cacc[4][4];
    #pragma unroll
    for (int j = 0; j < 4; j++)
        #pragma unroll
        for (int k = 0; k < 4; k++) cacc[j][k] = 0.f;

    float* vbuf[3] = {vb0, vb1, vb2};
    #pragma unroll 1
    for (int ch = 0; ch < 8; ch++) {
        cp_wait<1>();
        __syncthreads();
        if (ch + 2 < 8) {
            float* dstb = vbuf[(ch + 3) % 3];
            const float* src = vsrcb + (size_t)(ch + 2) * 64 * DK;
            #pragma unroll
            for (int j = 0; j < 4; j++) {
                int idx = tid + 256 * j;
                int r = idx >> 4, c = (idx & 15) << 2;
                cp16(dstb + r * AST + c, src + r * DK + c);
            }
        }
        cp_commit();

        const float* sV = vbuf[(ch + 1) % 3];
        #pragma unroll 1
        for (int kk = 0; kk < 64; kk += 8) {
            unsigned a[4];
            int rb = wm3 * 16 + gid;
            int col = ch * 64 + kk + tig;
            a[0] = __float_as_uint(sK[rb * 516 + col]);
            a[1] = __float_as_uint(sK[(rb + 8) * 516 + col]);
            a[2] = __float_as_uint(sK[rb * 516 + col + 4]);
            a[3] = __float_as_uint(sK[(rb + 8) * 516 + col + 4]);
            #pragma unroll
            for (int nf = 0; nf < 4; nf++) {
                int nb = wn3 * 32 + nf * 8 + gid;
                unsigned bb0 = __float_as_uint(sV[(kk + tig) * AST + nb]);
                unsigned bb1 = __float_as_uint(sV[(kk + 4 + tig) * AST + nb]);
                mma8(cacc[nf], a, bb0, bb1);
            }
        }
    }

    #pragma unroll
    for (int rr = 0; rr < 2; rr++) {
        int s = q0 + wm3 * 16 + gid + rr * 8;
        #pragma unroll
        for (int nf = 0; nf < 4; nf++) {
            int d = wn3 * 32 + nf * 8 + tig * 2;
            *reinterpret_cast<float2*>(
                &g_ctx[((size_t)b * SS + s) * DD + h * DK + d]) =
                make_float2(tf2f(cacc[nf][rr * 2]), tf2f(cacc[nf][rr * 2 + 1]));
        }
    }
}

// =====================================================================
// LayerNorm over rows of g_res -> y output (block per row, float4)
// =====================================================================
__global__ __launch_bounds__(256)
void ln_kernel(const float* __restrict__ ln_g, const float* __restrict__ ln_b,
               float* __restrict__ y_out)
{
    __shared__ float rs[8], rq[8];
    const int r = blockIdx.x, t = threadIdx.x;
    const float4* row4 = reinterpret_cast<const float4*>(g_res + (size_t)r * DD);
    float4 v = row4[t];
    float s = v.x + v.y + v.z + v.w;
    float q = v.x * v.x + v.y * v.y + v.z * v.z + v.w * v.w;
    #pragma unroll
    for (int o = 16; o > 0; o >>= 1) {
        s += __shfl_xor_sync(0xffffffffu, s, o);
        q += __shfl_xor_sync(0xffffffffu, q, o);
    }
    if ((t & 31) == 0) { rs[t >> 5] = s; rq[t >> 5] = q; }
    __syncthreads();
    if (t < 32) {
        float ss = (t < 8) ? rs[t] : 0.f;
        float qq = (t < 8) ? rq[t] : 0.f;
        #pragma unroll
        for (int o = 4; o > 0; o >>= 1) {
            ss += __shfl_xor_sync(0xffffffffu, ss, o);
            qq += __shfl_xor_sync(0xffffffffu, qq, o);
        }
        if (t == 0) { rs[0] = ss; rq[0] = qq; }
    }
    __syncthreads();
    float mean = rs[0] * (1.0f / 1024.0f);
    float var  = rq[0] * (1.0f / 1024.0f) - mean * mean;
    float rstd = rsqrtf(var + 1e-5f);
    const float4 g4 = reinterpret_cast<const float4*>(ln_g)[t];
    const float4 b4 = reinterpret_cast<const float4*>(ln_b)[t];
    float4 o;
    o.x = (v.x - mean) * rstd * g4.x + b4.x;
    o.y = (v.y - mean) * rstd * g4.y + b4.y;
    o.z = (v.z - mean) * rstd * g4.z + b4.z;
    o.w = (v.w - mean) * rstd * g4.w + b4.w;
    reinterpret_cast<float4*>(y_out + (size_t)r * DD)[t] = o;
}

// =====================================================================
extern "C" void kernel_launch(void* const* d_in, const int* in_sizes, int n_in,
                              void* d_out, int out_size)
{
    const float* x    = (const float*)d_in[0];
    const float* Wq   = (const float*)d_in[1];
    const float* bq   = (const float*)d_in[2];
    const float* Wk   = (const float*)d_in[3];
    const float* bk   = (const float*)d_in[4];
    const float* Wv   = (const float*)d_in[5];
    const float* bv   = (const float*)d_in[6];
    const float* Wo   = (const float*)d_in[7];
    const float* bo   = (const float*)d_in[8];
    const float* ln_g = (const float*)d_in[9];
    const float* ln_b = (const float*)d_in[10];
    const float* hv   = (const float*)d_in[11];
    const int*   hm   = (const int*)d_in[12];
    const int*   am   = (const int*)d_in[13];

    float* out = (float*)d_out;
    float* y_out    = out;                          // [B,S,D]
    float* attn_out = out + (size_t)MTOT * DD;      // [B,H,S,S]

    cudaFuncSetAttribute(gemm_tf32_kernel<0>,
                         cudaFuncAttributeMaxDynamicSharedMemorySize, GEMM_SMEM_BYTES);
    cudaFuncSetAttribute(gemm_tf32_kernel<1>,
                         cudaFuncAttributeMaxDynamicSharedMemorySize, GEMM_SMEM_BYTES);
    cudaFuncSetAttribute(attn_fused_kernel,
                         cudaFuncAttributeMaxDynamicSharedMemorySize, ATTN_SMEM_BYTES);

    // 0) prep: round x; round+transpose weights; pack masks to bits
    prep_round_x<<<dim3(148), 256>>>(x);
    prep_transpose_w<<<dim3(32, 32, 4), 256>>>(Wq, Wk, Wv, Wo);
    pack_masks<<<dim3(8192, 2), 256>>>(hm, am);
    // 1) QKV projections
    gemm_tf32_kernel<0><<<dim3(32, 8, 3), 256, GEMM_SMEM_BYTES>>>(bq, bk, bv, nullptr);
    // 2) fused attention
    attn_fused_kernel<<<dim3(BHTOT, 8), 256, ATTN_SMEM_BYTES>>>(hv, attn_out);
    // 3) out projection + bias + residual
    gemm_tf32_kernel<1><<<dim3(32, 8, 1), 256, GEMM_SMEM_BYTES>>>(bo, bo, bo, x);
    // 4) LayerNorm -> y
    ln_kernel<<<dim3(MTOT), 256>>>(ln_g, ln_b, y_out);
}

// round 15
// speedup vs baseline: 1.0736x; 1.0291x over previous
#include <cuda_runtime.h>
#include <cstdint>

#define NEG_INF_F (-1e9f)
#define HTHRESH_F (-1e8f)

// B=8, S=512, D=1024, H=16, DK=64
#define BB 8
#define SS 512
#define DD 1024
#define HH 16
#define DK 64
#define MTOT (BB*SS)          // 4096
#define BHTOT (BB*HH)         // 128

// -------- scratch (device globals; no cudaMalloc allowed) --------
__device__ float g_q[BB*HH*SS*DK];
__device__ float g_k[BB*HH*SS*DK];
__device__ float g_v[BB*HH*SS*DK];
__device__ float g_ctx[MTOT*DD];
__device__ float g_res[MTOT*DD];
__device__ float g_xr[MTOT*DD];     // tf32-rounded x
// tf32-rounded, TRANSPOSED weights [N][K] (n-major rows for ldmatrix B-frags)
__device__ float g_wqt[DD*DD];
__device__ float g_wkt[DD*DD];
__device__ float g_wvt[DD*DD];
__device__ float g_wot[DD*DD];
// bit-packed masks: 512 cols -> 16 uint32 words per row
__device__ unsigned g_hmp[BHTOT*SS*16];   // 4 MB
__device__ unsigned g_amp[BB*SS*16];      // 256 KB

// -------- helpers --------
__device__ __forceinline__ unsigned f2tf(float f) {
    unsigned u;
    asm("cvt.rna.tf32.f32 %0, %1;" : "=r"(u) : "f"(f));
    return u;
}
__device__ __forceinline__ float tf2f(float f) {
    return __uint_as_float(f2tf(f));
}
__device__ __forceinline__ void mma8(float c[4], const unsigned a[4], unsigned b0, unsigned b1) {
    asm volatile(
        "mma.sync.aligned.m16n8k8.row.col.f32.tf32.tf32.f32 "
        "{%0,%1,%2,%3}, {%4,%5,%6,%7}, {%8,%9}, {%0,%1,%2,%3};\n"
        : "+f"(c[0]), "+f"(c[1]), "+f"(c[2]), "+f"(c[3])
        : "r"(a[0]), "r"(a[1]), "r"(a[2]), "r"(a[3]), "r"(b0), "r"(b1));
}
__device__ __forceinline__ void ldsm4(unsigned r[4], unsigned saddr) {
    asm volatile("ldmatrix.sync.aligned.m8n8.x4.shared.b16 {%0,%1,%2,%3}, [%4];\n"
                 : "=r"(r[0]), "=r"(r[1]), "=r"(r[2]), "=r"(r[3]) : "r"(saddr));
}
__device__ __forceinline__ void cp16(float* smem_dst, const float* gsrc) {
    unsigned d = (unsigned)__cvta_generic_to_shared(smem_dst);
    asm volatile("cp.async.cg.shared.global [%0], [%1], 16;\n" :: "r"(d), "l"(gsrc));
}
__device__ __forceinline__ void cp_commit() {
    asm volatile("cp.async.commit_group;\n");
}
template<int N>
__device__ __forceinline__ void cp_wait() {
    asm volatile("cp.async.wait_group %0;\n" :: "n"(N));
}

// =====================================================================
// Prep kernels
// =====================================================================
__global__ __launch_bounds__(256)
void prep_round_x(const float* __restrict__ x)
{
    float4* dst = (float4*)g_xr;
    const float4* src = (const float4*)x;
    const int n4 = MTOT * DD / 4;
    for (int i = blockIdx.x * blockDim.x + threadIdx.x; i < n4;
         i += gridDim.x * blockDim.x) {
        float4 v = src[i];
        v.x = tf2f(v.x); v.y = tf2f(v.y); v.z = tf2f(v.z); v.w = tf2f(v.w);
        dst[i] = v;
    }
}
__global__ __launch_bounds__(256)
void prep_transpose_w(const float* __restrict__ Wq, const float* __restrict__ Wk,
                      const float* __restrict__ Wv, const float* __restrict__ Wo)
{
    __shared__ float t[32][33];
    const int z = blockIdx.z;
    const float* W = (z == 0) ? Wq : (z == 1 ? Wk : (z == 2 ? Wv : Wo));
    float* WT = (z == 0) ? g_wqt : (z == 1 ? g_wkt : (z == 2 ? g_wvt : g_wot));
    const int k0 = blockIdx.x * 32;
    const int n0 = blockIdx.y * 32;
    const int tx = threadIdx.x & 31, ty = threadIdx.x >> 5;
    #pragma unroll
    for (int j = 0; j < 4; j++) {
        int k = k0 + ty + j * 8;
        t[ty + j * 8][tx] = tf2f(W[(size_t)k * DD + n0 + tx]);
    }
    __syncthreads();
    #pragma unroll
    for (int j = 0; j < 4; j++) {
        int n = n0 + ty + j * 8;
        WT[(size_t)n * DD + k0 + tx] = t[tx][ty + j * 8];
    }
}
__global__ __launch_bounds__(256)
void pack_masks(const int* __restrict__ hm, const int* __restrict__ am)
{
    const int warp = threadIdx.x >> 5, lane = threadIdx.x & 31;
    const int row = blockIdx.x * 8 + warp;
    if (blockIdx.y == 0) {
        const int* src = hm + (size_t)row * SS;
        unsigned* dst = g_hmp + (size_t)row * 16;
        #pragma unroll
        for (int i = 0; i < 16; i++) {
            unsigned w = __ballot_sync(0xffffffffu, src[i * 32 + lane] != 0);
            if (lane == 0) dst[i] = w;
        }
    } else {
        if (row >= BB * SS) return;
        const int* src = am + (size_t)row * SS;
        unsigned* dst = g_amp + (size_t)row * 16;
        #pragma unroll
        for (int i = 0; i < 16; i++) {
            unsigned w = __ballot_sync(0xffffffffu, src[i * 32 + lane] != 0);
            if (lane == 0) dst[i] = w;
        }
    }
}

// =====================================================================
// GEMM: C[4096,1024] = A @ W (+bias [+residual])   (unchanged)
// =====================================================================
#define GBM 128
#define GBN 128
#define GBK 32
#define GST 3
#define TILE_F (GBM * GBK)
#define GEMM_SMEM_BYTES (GST * TILE_F * 2 * 4)   // 98304

template<int MODE>
__global__ __launch_bounds__(256, 2)
void gemm_tf32_kernel(const float* __restrict__ bias0, const float* __restrict__ bias1,
                      const float* __restrict__ bias2,
                      const float* __restrict__ xres)
{
    extern __shared__ float gsm[];
    float* sA = gsm;
    float* sB = gsm + GST * TILE_F;

    const int z = blockIdx.z;
    const float* WT   = (MODE == 1) ? g_wot : ((z == 0) ? g_wqt : (z == 1 ? g_wkt : g_wvt));
    const float* bias = (z == 0) ? bias0 : (z == 1 ? bias1 : bias2);
    const float* A    = (MODE == 0) ? g_xr : g_ctx;
    float* dst = (MODE == 0) ? ((z == 0) ? g_q : (z == 1 ? g_k : g_v)) : g_res;

    const int m0 = blockIdx.x * GBM;
    const int n0 = blockIdx.y * GBN;
    const int tid = threadIdx.x;
    const int warp = tid >> 5, lane = tid & 31, gid = lane >> 2, tig = lane & 3;
    const int wm = warp & 1, wn = warp >> 1;

    const int l7  = lane & 7;
    const int lhA = (lane >> 3) & 1;
    const int khA = lane >> 4;
    const int khB = (lane >> 3) & 1;
    const int nsB = lane >> 4;

    float acc[4][4][4];
    #pragma unroll
    for (int i = 0; i < 4; i++)
        #pragma unroll
        for (int j = 0; j < 4; j++)
            #pragma unroll
            for (int k = 0; k < 4; k++) acc[i][j][k] = 0.f;

    auto load_tile = [&](int st, int kt) {
        float* dA = sA + st * TILE_F;
        float* dB = sB + st * TILE_F;
        #pragma unroll
        for (int j = 0; j < 4; j++) {
            int idx = tid + 256 * j;
            int r = idx >> 3, c = idx & 7;
            cp16(dA + r * 32 + ((c ^ (r & 7)) << 2),
                 A + (size_t)(m0 + r) * DD + kt + (c << 2));
        }
        #pragma unroll
        for (int j = 0; j < 4; j++) {
            int idx = tid + 256 * j;
            int r = idx >> 3, c = idx & 7;
            cp16(dB + r * 32 + ((c ^ (r & 7)) << 2),
                 WT + (size_t)(n0 + r) * DD + kt + (c << 2));
        }
    };

    #pragma unroll
    for (int s = 0; s < GST - 1; s++) { load_tile(s, s * GBK); cp_commit(); }

    const int NIT = DD / GBK;
    for (int it = 0; it < NIT; it++) {
        cp_wait<GST - 2>();
        __syncthreads();
        int nxt = it + GST - 1;
        if (nxt < NIT) load_tile(nxt % GST, nxt * GBK);
        cp_commit();

        const unsigned tAs = (unsigned)__cvta_generic_to_shared(sA + (it % GST) * TILE_F);
        const unsigned tBs = (unsigned)__cvta_generic_to_shared(sB + (it % GST) * TILE_F);
        #pragma unroll
        for (int kk = 0; kk < GBK; kk += 8) {
            const int c0 = kk >> 2;
            unsigned a[4][4];
            #pragma unroll
            for (int mf = 0; mf < 4; mf++) {
                int row = wm * 64 + mf * 16 + lhA * 8 + l7;
                unsigned saddr = tAs + ((row * 32 + (((c0 + khA) ^ l7) << 2)) << 2);
                ldsm4(a[mf], saddr);
            }
            unsigned b[2][4];
            #pragma unroll
            for (int p = 0; p < 2; p++) {
                int row = wn * 32 + p * 16 + nsB * 8 + l7;
                unsigned saddr = tBs + ((row * 32 + (((c0 + khB) ^ l7) << 2)) << 2);
                ldsm4(b[p], saddr);
            }
            #pragma unroll
            for (int p = 0; p < 2; p++)
                #pragma unroll
                for (int h = 0; h < 2; h++) {
                    const int nf = p * 2 + h;
                    #pragma unroll
                    for (int mf = 0; mf < 4; mf++)
                        mma8(acc[mf][nf], a[mf], b[p][2 * h], b[p][2 * h + 1]);
                }
        }
    }

    #pragma unroll
    for (int mf = 0; mf < 4; mf++) {
        #pragma unroll
        for (int rr = 0; rr < 2; rr++) {
            int m = m0 + wm * 64 + mf * 16 + gid + rr * 8;
            #pragma unroll
            for (int nf = 0; nf < 4; nf++) {
                int n = n0 + wn * 32 + nf * 8 + tig * 2;
                float v0 = acc[mf][nf][rr * 2 + 0] + bias[n];
                float v1 = acc[mf][nf][rr * 2 + 1] + bias[n + 1];
                if (MODE == 0) {
                    int bidx = m >> 9, s = m & 511, hh = n >> 6, d = n & 63;
                    *reinterpret_cast<float2*>(
                        &dst[(((size_t)bidx * HH + hh) * SS + s) * DK + d]) =
                        make_float2(tf2f(v0), tf2f(v1));
                } else {
                    v0 += xres[(size_t)m * DD + n];
                    v1 += xres[(size_t)m * DD + n + 1];
                    *reinterpret_cast<float2*>(&dst[(size_t)m * DD + n]) = make_float2(v0, v1);
                }
            }
        }
    }
}

// =====================================================================
// Fused attention, 512 threads (16 warps), R12 phase/barrier structure.
//   phase1: 2(M)x8(N) warp grid, acc[2][8][4]
//   blend:  32 iters/thread, PF=8 hv ring, bit-packed masks in smem
//   phase2: softmax, 4 rows/warp
//   phase3: 4(M)x4(N) warp grid, cacc[2][4], triple-buffered V
// =====================================================================
#define AST 72
#define SK_FLOATS (512 * AST)
#define VB_FLOATS (64 * AST)
#define MASK_WORDS (64 * 16)
#define ATTN_SMEM_BYTES ((SK_FLOATS + 3 * VB_FLOATS + 2 * MASK_WORDS) * 4)  // 210944
#define PF 8

__global__ __launch_bounds__(512)
void attn_fused_kernel(const float* __restrict__ help_vals,
                       float* __restrict__ attn_out)
{
    extern __shared__ float smem[];
    float* sK = smem;
    float* vb0 = smem + SK_FLOATS;
    float* vb1 = vb0 + VB_FLOATS;
    float* vb2 = vb1 + VB_FLOATS;
    unsigned* sMH = (unsigned*)(vb2 + VB_FLOATS);
    unsigned* sMA = sMH + MASK_WORDS;

    const int bh = blockIdx.x;
    const int b = bh >> 4;
    const int h = bh & 15;
    const int q0 = blockIdx.y * 64;
    const int tid = threadIdx.x;
    const int warp = tid >> 5, lane = tid & 31, gid = lane >> 2, tig = lane & 3;

    const float* vsrcb = g_v + (size_t)bh * SS * DK;

    // ---- async load Q tile, full K, and bit-packed masks ----
    {
        const float* qsrc = g_q + ((size_t)bh * SS + q0) * DK;
        #pragma unroll
        for (int j = 0; j < 2; j++) {
            int idx = tid + 512 * j;
            int r = idx >> 4, c = (idx & 15) << 2;
            cp16(vb0 + r * AST + c, qsrc + r * DK + c);
        }
        const float* ksrc = g_k + (size_t)bh * SS * DK;
        #pragma unroll
        for (int j = 0; j < 16; j++) {
            int idx = tid + 512 * j;
            int r = idx >> 4, c = (idx & 15) << 2;
            cp16(sK + r * AST + c, ksrc + r * DK + c);
        }
        if (tid < 256) {   // hm: 64 rows x 16 words
            int r = tid >> 2, c = (tid & 3) << 2;
            cp16((float*)(sMH + r * 16 + c),
                 (const float*)(g_hmp + ((size_t)bh * SS + q0 + r) * 16 + c));
        } else {           // am
            int t = tid - 256;
            int r = t >> 2, c = (t & 3) << 2;
            cp16((float*)(sMA + r * 16 + c),
                 (const float*)(g_amp + ((size_t)b * SS + q0 + r) * 16 + c));
        }
        cp_commit();
        cp_wait<0>();
        __syncthreads();
    }

    const int wm = warp & 1;    // 2 groups of 32 q-rows
    const int wn = warp >> 1;   // 8 groups of 64 key-cols

    // ---- pre-issue first hv batch (overlaps phase-1 mma) ----
    const float* hvp = help_vals + ((size_t)bh * SS + q0) * SS;
    const int base_lm = wm * 32 + gid;
    const int base_ln = wn * 64 + tig * 2;

    float2 hvb[PF];
    #pragma unroll
    for (int i = 0; i < PF; i++) {
        int lm = base_lm + ((i >> 4) << 4) + (((i >> 3) & 1) << 3);
        int ln = base_ln + ((i & 7) << 3);
        hvb[i] = __ldcs(reinterpret_cast<const float2*>(hvp + (size_t)lm * SS + ln));
    }

    // ---- phase 1: scores = Q @ K^T ----
    float acc[2][8][4];
    #pragma unroll
    for (int i = 0; i < 2; i++)
        #pragma unroll
        for (int j = 0; j < 8; j++)
            #pragma unroll
            for (int k = 0; k < 4; k++) acc[i][j][k] = 0.f;

    #pragma unroll 1
    for (int kk = 0; kk < DK; kk += 8) {
        unsigned a[2][4];
        #pragma unroll
        for (int mf = 0; mf < 2; mf++) {
            int rb = wm * 32 + mf * 16 + gid;
            a[mf][0] = __float_as_uint(vb0[rb * AST + kk + tig]);
            a[mf][1] = __float_as_uint(vb0[(rb + 8) * AST + kk + tig]);
            a[mf][2] = __float_as_uint(vb0[rb * AST + kk + 4 + tig]);
            a[mf][3] = __float_as_uint(vb0[(rb + 8) * AST + kk + 4 + tig]);
        }
        #pragma unroll
        for (int nf = 0; nf < 8; nf++) {
            int nb = wn * 64 + nf * 8 + gid;
            unsigned bb0 = __float_as_uint(sK[nb * AST + kk + tig]);
            unsigned bb1 = __float_as_uint(sK[nb * AST + kk + 4 + tig]);
            mma8(acc[0][nf], a[0], bb0, bb1);
            mma8(acc[1][nf], a[1], bb0, bb1);
        }
    }
    __syncthreads();   // K/Q dead; overlay scores on sK

    // prefetch V chunks 0,1 (land during blend + softmax)
    {
        #pragma unroll
        for (int j = 0; j < 2; j++) {
            int idx = tid + 512 * j;
            int r = idx >> 4, c = (idx & 15) << 2;
            cp16(vb1 + r * AST + c, vsrcb + r * DK + c);
        }
        cp_commit();
        #pragma unroll
        for (int j = 0; j < 2; j++) {
            int idx = tid + 512 * j;
            int r = idx >> 4, c = (idx & 15) << 2;
            cp16(vb2 + r * AST + c, vsrcb + (64 + r) * DK + c);
        }
        cp_commit();
    }

    // ---- blend: scale + attn_mask + dependency blend -> sK ----
    {
        #pragma unroll
        for (int i = 0; i < 32; i++) {
            const int slot = i & (PF - 1);
            float2 hv2 = hvb[slot];
            if (i + PF < 32) {
                int j = i + PF;
                int lmp = base_lm + ((j >> 4) << 4) + (((j >> 3) & 1) << 3);
                int lnp = base_ln + ((j & 7) << 3);
                hvb[slot] = __ldcs(reinterpret_cast<const float2*>(
                    hvp + (size_t)lmp * SS + lnp));
            }
            const int mf = i >> 4, rr = (i >> 3) & 1, nf = i & 7;
            const int lm = base_lm + (mf << 4) + (rr << 3);
            const int ln = base_ln + (nf << 3);
            const unsigned wh = sMH[lm * 16 + (ln >> 5)];
            const unsigned wa = sMA[lm * 16 + (ln >> 5)];
            const int sh = ln & 31;
            float s0 = ((wa >> sh) & 1u) ? NEG_INF_F : acc[mf][nf][rr * 2 + 0] * 0.125f;
            float s1 = ((wa >> (sh + 1)) & 1u) ? NEG_INF_F : acc[mf][nf][rr * 2 + 1] * 0.125f;
            if (((wh >> sh) & 1u) && hv2.x > HTHRESH_F) s0 = 0.5f * hv2.x + 0.5f * s0;
            if (((wh >> (sh + 1)) & 1u) && hv2.y > HTHRESH_F) s1 = 0.5f * hv2.y + 0.5f * s1;
            sK[lm * 516 + ln]     = s0;
            sK[lm * 516 + ln + 1] = s1;
        }
    }
    __syncthreads();

    // ---- phase 2: softmax per row (4 rows/warp); attn via __stcs ----
    {
        float* aout = attn_out + ((size_t)bh * SS + q0) * SS;
        #pragma unroll 1
        for (int j = 0; j < 4; j++) {
            int r = warp * 4 + j;
            float* row = &sK[r * 516];
            float vals[16];
            float mx = -3e38f;
            #pragma unroll
            for (int i = 0; i < 16; i++) { vals[i] = row[lane + 32 * i]; mx = fmaxf(mx, vals[i]); }
            #pragma unroll
            for (int o = 16; o > 0; o >>= 1) mx = fmaxf(mx, __shfl_xor_sync(0xffffffffu, mx, o));
            float sum = 0.f;
            #pragma unroll
            for (int i = 0; i < 16; i++) { vals[i] = __expf(vals[i] - mx); sum += vals[i]; }
            #pragma unroll
            for (int o = 16; o > 0; o >>= 1) sum += __shfl_xor_sync(0xffffffffu, sum, o);
            float inv = 1.0f / sum;
            #pragma unroll
            for (int i = 0; i < 16; i++) {
                float p = vals[i] * inv;
                __stcs(&aout[(size_t)r * SS + lane + 32 * i], p);
                row[lane + 32 * i] = tf2f(p);
            }
        }
    }

    // ---- phase 3: ctx = P @ V, triple-buffered V chunks ----
    const int wm3 = warp & 3;   // 4 groups of 16 rows
    const int wn3 = warp >> 2;  // 4 groups of 16 d-cols
    float cacc[2][4];
    #pragma unroll
    for (int j = 0; j < 2; j++)
        #pragma unroll
        for (int k = 0; k < 4; k++) cacc[j][k] = 0.f;

    float* vbuf[3] = {vb0, vb1, vb2};
    #pragma unroll 1
    for (int ch = 0; ch < 8; ch++) {
        cp_wait<1>();
        __syncthreads();
        if (ch + 2 < 8) {
            float* dstb = vbuf[(ch + 3) % 3];
            const float* src = vsrcb + (size_t)(ch + 2) * 64 * DK;
            #pragma unroll
            for (int j = 0; j < 2; j++) {
                int idx = tid + 512 * j;
                int r = idx >> 4, c = (idx & 15) << 2;
                cp16(dstb + r * AST + c, src + r * DK + c);
            }
        }
        cp_commit();

        const float* sV = vbuf[(ch + 1) % 3];
        #pragma unroll 1
        for (int kk = 0; kk < 64; kk += 8) {
            unsigned a[4];
            int rb = wm3 * 16 + gid;
            int col = ch * 64 + kk + tig;
            a[0] = __float_as_uint(sK[rb * 516 + col]);
            a[1] = __float_as_uint(sK[(rb + 8) * 516 + col]);
            a[2] = __float_as_uint(sK[rb * 516 + col + 4]);
            a[3] = __float_as_uint(sK[(rb + 8) * 516 + col + 4]);
            #pragma unroll
            for (int nf = 0; nf < 2; nf++) {
                int nb = wn3 * 16 + nf * 8 + gid;
                unsigned bb0 = __float_as_uint(sV[(kk + tig) * AST + nb]);
                unsigned bb1 = __float_as_uint(sV[(kk + 4 + tig) * AST + nb]);
                mma8(cacc[nf], a, bb0, bb1);
            }
        }
    }

    // write tf32-rounded ctx tile -> g_ctx [m = b*S+s][h*64+d]
    #pragma unroll
    for (int rr = 0; rr < 2; rr++) {
        int s = q0 + wm3 * 16 + gid + rr * 8;
        #pragma unroll
        for (int nf = 0; nf < 2; nf++) {
            int d = wn3 * 16 + nf * 8 + tig * 2;
            *reinterpret_cast<float2*>(
                &g_ctx[((size_t)b * SS + s) * DD + h * DK + d]) =
                make_float2(tf2f(cacc[nf][rr * 2]), tf2f(cacc[nf][rr * 2 + 1]));
        }
    }
}

// =====================================================================
// LayerNorm over rows of g_res -> y output (block per row, float4)
// =====================================================================
__global__ __launch_bounds__(256)
void ln_kernel(const float* __restrict__ ln_g, const float* __restrict__ ln_b,
               float* __restrict__ y_out)
{
    __shared__ float rs[8], rq[8];
    const int r = blockIdx.x, t = threadIdx.x;
    const float4* row4 = reinterpret_cast<const float4*>(g_res + (size_t)r * DD);
    float4 v = row4[t];
    float s = v.x + v.y + v.z + v.w;
    float q = v.x * v.x + v.y * v.y + v.z * v.z + v.w * v.w;
    #pragma unroll
    for (int o = 16; o > 0; o >>= 1) {
        s += __shfl_xor_sync(0xffffffffu, s, o);
        q += __shfl_xor_sync(0xffffffffu, q, o);
    }
    if ((t & 31) == 0) { rs[t >> 5] = s; rq[t >> 5] = q; }
    __syncthreads();
    if (t < 32) {
        float ss = (t < 8) ? rs[t] : 0.f;
        float qq = (t < 8) ? rq[t] : 0.f;
        #pragma unroll
        for (int o = 4; o > 0; o >>= 1) {
            ss += __shfl_xor_sync(0xffffffffu, ss, o);
            qq += __shfl_xor_sync(0xffffffffu, qq, o);
        }
        if (t == 0) { rs[0] = ss; rq[0] = qq; }
    }
    __syncthreads();
    float mean = rs[0] * (1.0f / 1024.0f);
    float var  = rq[0] * (1.0f / 1024.0f) - mean * mean;
    float rstd = rsqrtf(var + 1e-5f);
    const float4 g4 = reinterpret_cast<const float4*>(ln_g)[t];
    const float4 b4 = reinterpret_cast<const float4*>(ln_b)[t];
    float4 o;
    o.x = (v.x - mean) * rstd * g4.x + b4.x;
    o.y = (v.y - mean) * rstd * g4.y + b4.y;
    o.z = (v.z - mean) * rstd * g4.z + b4.z;
    o.w = (v.w - mean) * rstd * g4.w + b4.w;
    reinterpret_cast<float4*>(y_out + (size_t)r * DD)[t] = o;
}

// =====================================================================
extern "C" void kernel_launch(void* const* d_in, const int* in_sizes, int n_in,
                              void* d_out, int out_size)
{
    const float* x    = (const float*)d_in[0];
    const float* Wq   = (const float*)d_in[1];
    const float* bq   = (const float*)d_in[2];
    const float* Wk   = (const float*)d_in[3];
    const float* bk   = (const float*)d_in[4];
    const float* Wv   = (const float*)d_in[5];
    const float* bv   = (const float*)d_in[6];
    const float* Wo   = (const float*)d_in[7];
    const float* bo   = (const float*)d_in[8];
    const float* ln_g = (const float*)d_in[9];
    const float* ln_b = (const float*)d_in[10];
    const float* hv   = (const float*)d_in[11];
    const int*   hm   = (const int*)d_in[12];
    const int*   am   = (const int*)d_in[13];

    float* out = (float*)d_out;
    float* y_out    = out;                          // [B,S,D]
    float* attn_out = out + (size_t)MTOT * DD;      // [B,H,S,S]

    cudaFuncSetAttribute(gemm_tf32_kernel<0>,
                         cudaFuncAttributeMaxDynamicSharedMemorySize, GEMM_SMEM_BYTES);
    cudaFuncSetAttribute(gemm_tf32_kernel<1>,
                         cudaFuncAttributeMaxDynamicSharedMemorySize, GEMM_SMEM_BYTES);
    cudaFuncSetAttribute(attn_fused_kernel,
                         cudaFuncAttributeMaxDynamicSharedMemorySize, ATTN_SMEM_BYTES);

    // 0) prep: round x; round+transpose weights; pack masks to bits
    prep_round_x<<<dim3(148), 256>>>(x);
    prep_transpose_w<<<dim3(32, 32, 4), 256>>>(Wq, Wk, Wv, Wo);
    pack_masks<<<dim3(8192, 2), 256>>>(hm, am);
    // 1) QKV projections
    gemm_tf32_kernel<0><<<dim3(32, 8, 3), 256, GEMM_SMEM_BYTES>>>(bq, bk, bv, nullptr);
    // 2) fused attention (512 threads, 16 warps)
    attn_fused_kernel<<<dim3(BHTOT, 8), 512, ATTN_SMEM_BYTES>>>(hv, attn_out);
    // 3) out projection + bias + residual
    gemm_tf32_kernel<1><<<dim3(32, 8, 1), 256, GEMM_SMEM_BYTES>>>(bo, bo, bo, x);
    // 4) LayerNorm -> y
    ln_kernel<<<dim3(MTOT), 256>>>(ln_g, ln_b, y_out);
}

// round 16
// speedup vs baseline: 1.1031x; 1.0275x over previous
#include <cuda_runtime.h>
#include <cstdint>

#define NEG_INF_F (-1e9f)
#define HTHRESH_F (-1e8f)

// B=8, S=512, D=1024, H=16, DK=64
#define BB 8
#define SS 512
#define DD 1024
#define HH 16
#define DK 64
#define MTOT (BB*SS)          // 4096
#define BHTOT (BB*HH)         // 128

// -------- scratch (device globals; no cudaMalloc allowed) --------
__device__ float g_q[BB*HH*SS*DK];
__device__ float g_k[BB*HH*SS*DK];
__device__ float g_v[BB*HH*SS*DK];
__device__ float g_ctx[MTOT*DD];
__device__ float g_res[MTOT*DD];
__device__ float g_xr[MTOT*DD];     // tf32-rounded x
// tf32-rounded, TRANSPOSED weights [N][K] (n-major rows for ldmatrix B-frags)
__device__ float g_wqt[DD*DD];
__device__ float g_wkt[DD*DD];
__device__ float g_wvt[DD*DD];
__device__ float g_wot[DD*DD];
// bit-packed masks: 512 cols -> 16 uint32 words per row
__device__ unsigned g_hmp[BHTOT*SS*16];   // 4 MB
__device__ unsigned g_amp[BB*SS*16];      // 256 KB

// -------- helpers --------
__device__ __forceinline__ unsigned f2tf(float f) {
    unsigned u;
    asm("cvt.rna.tf32.f32 %0, %1;" : "=r"(u) : "f"(f));
    return u;
}
__device__ __forceinline__ float tf2f(float f) {
    return __uint_as_float(f2tf(f));
}
__device__ __forceinline__ void mma8(float c[4], const unsigned a[4], unsigned b0, unsigned b1) {
    asm volatile(
        "mma.sync.aligned.m16n8k8.row.col.f32.tf32.tf32.f32 "
        "{%0,%1,%2,%3}, {%4,%5,%6,%7}, {%8,%9}, {%0,%1,%2,%3};\n"
        : "+f"(c[0]), "+f"(c[1]), "+f"(c[2]), "+f"(c[3])
        : "r"(a[0]), "r"(a[1]), "r"(a[2]), "r"(a[3]), "r"(b0), "r"(b1));
}
__device__ __forceinline__ void ldsm4(unsigned r[4], unsigned saddr) {
    asm volatile("ldmatrix.sync.aligned.m8n8.x4.shared.b16 {%0,%1,%2,%3}, [%4];\n"
                 : "=r"(r[0]), "=r"(r[1]), "=r"(r[2]), "=r"(r[3]) : "r"(saddr));
}
__device__ __forceinline__ void cp16(float* smem_dst, const float* gsrc) {
    unsigned d = (unsigned)__cvta_generic_to_shared(smem_dst);
    asm volatile("cp.async.cg.shared.global [%0], [%1], 16;\n" :: "r"(d), "l"(gsrc));
}
__device__ __forceinline__ void cp_commit() {
    asm volatile("cp.async.commit_group;\n");
}
template<int N>
__device__ __forceinline__ void cp_wait() {
    asm volatile("cp.async.wait_group %0;\n" :: "n"(N));
}

// =====================================================================
// Prep kernels
// =====================================================================
__global__ __launch_bounds__(256)
void prep_round_x(const float* __restrict__ x)
{
    float4* dst = (float4*)g_xr;
    const float4* src = (const float4*)x;
    const int n4 = MTOT * DD / 4;
    for (int i = blockIdx.x * blockDim.x + threadIdx.x; i < n4;
         i += gridDim.x * blockDim.x) {
        float4 v = src[i];
        v.x = tf2f(v.x); v.y = tf2f(v.y); v.z = tf2f(v.z); v.w = tf2f(v.w);
        dst[i] = v;
    }
}
__global__ __launch_bounds__(256)
void prep_transpose_w(const float* __restrict__ Wq, const float* __restrict__ Wk,
                      const float* __restrict__ Wv, const float* __restrict__ Wo)
{
    __shared__ float t[32][33];
    const int z = blockIdx.z;
    const float* W = (z == 0) ? Wq : (z == 1 ? Wk : (z == 2 ? Wv : Wo));
    float* WT = (z == 0) ? g_wqt : (z == 1 ? g_wkt : (z == 2 ? g_wvt : g_wot));
    const int k0 = blockIdx.x * 32;
    const int n0 = blockIdx.y * 32;
    const int tx = threadIdx.x & 31, ty = threadIdx.x >> 5;
    #pragma unroll
    for (int j = 0; j < 4; j++) {
        int k = k0 + ty + j * 8;
        t[ty + j * 8][tx] = tf2f(W[(size_t)k * DD + n0 + tx]);
    }
    __syncthreads();
    #pragma unroll
    for (int j = 0; j < 4; j++) {
        int n = n0 + ty + j * 8;
        WT[(size_t)n * DD + k0 + tx] = t[tx][ty + j * 8];
    }
}
__global__ __launch_bounds__(256)
void pack_masks(const int* __restrict__ hm, const int* __restrict__ am)
{
    const int warp = threadIdx.x >> 5, lane = threadIdx.x & 31;
    const int row = blockIdx.x * 8 + warp;
    if (blockIdx.y == 0) {
        const int* src = hm + (size_t)row * SS;
        unsigned* dst = g_hmp + (size_t)row * 16;
        #pragma unroll
        for (int i = 0; i < 16; i++) {
            unsigned w = __ballot_sync(0xffffffffu, src[i * 32 + lane] != 0);
            if (lane == 0) dst[i] = w;
        }
    } else {
        if (row >= BB * SS) return;
        const int* src = am + (size_t)row * SS;
        unsigned* dst = g_amp + (size_t)row * 16;
        #pragma unroll
        for (int i = 0; i < 16; i++) {
            unsigned w = __ballot_sync(0xffffffffu, src[i * 32 + lane] != 0);
            if (lane == 0) dst[i] = w;
        }
    }
}

// =====================================================================
// GEMM: C[4096,1024] = A @ W (+bias [+residual])   (unchanged)
// =====================================================================
#define GBM 128
#define GBN 128
#define GBK 32
#define GST 3
#define TILE_F (GBM * GBK)
#define GEMM_SMEM_BYTES (GST * TILE_F * 2 * 4)   // 98304

template<int MODE>
__global__ __launch_bounds__(256, 2)
void gemm_tf32_kernel(const float* __restrict__ bias0, const float* __restrict__ bias1,
                      const float* __restrict__ bias2,
                      const float* __restrict__ xres)
{
    extern __shared__ float gsm[];
    float* sA = gsm;
    float* sB = gsm + GST * TILE_F;

    const int z = blockIdx.z;
    const float* WT   = (MODE == 1) ? g_wot : ((z == 0) ? g_wqt : (z == 1 ? g_wkt : g_wvt));
    const float* bias = (z == 0) ? bias0 : (z == 1 ? bias1 : bias2);
    const float* A    = (MODE == 0) ? g_xr : g_ctx;
    float* dst = (MODE == 0) ? ((z == 0) ? g_q : (z == 1 ? g_k : g_v)) : g_res;

    const int m0 = blockIdx.x * GBM;
    const int n0 = blockIdx.y * GBN;
    const int tid = threadIdx.x;
    const int warp = tid >> 5, lane = tid & 31, gid = lane >> 2, tig = lane & 3;
    const int wm = warp & 1, wn = warp >> 1;

    const int l7  = lane & 7;
    const int lhA = (lane >> 3) & 1;
    const int khA = lane >> 4;
    const int khB = (lane >> 3) & 1;
    const int nsB = lane >> 4;

    float acc[4][4][4];
    #pragma unroll
    for (int i = 0; i < 4; i++)
        #pragma unroll
        for (int j = 0; j < 4; j++)
            #pragma unroll
            for (int k = 0; k < 4; k++) acc[i][j][k] = 0.f;

    auto load_tile = [&](int st, int kt) {
        float* dA = sA + st * TILE_F;
        float* dB = sB + st * TILE_F;
        #pragma unroll
        for (int j = 0; j < 4; j++) {
            int idx = tid + 256 * j;
            int r = idx >> 3, c = idx & 7;
            cp16(dA + r * 32 + ((c ^ (r & 7)) << 2),
                 A + (size_t)(m0 + r) * DD + kt + (c << 2));
        }
        #pragma unroll
        for (int j = 0; j < 4; j++) {
            int idx = tid + 256 * j;
            int r = idx >> 3, c = idx & 7;
            cp16(dB + r * 32 + ((c ^ (r & 7)) << 2),
                 WT + (size_t)(n0 + r) * DD + kt + (c << 2));
        }
    };

    #pragma unroll
    for (int s = 0; s < GST - 1; s++) { load_tile(s, s * GBK); cp_commit(); }

    const int NIT = DD / GBK;
    for (int it = 0; it < NIT; it++) {
        cp_wait<GST - 2>();
        __syncthreads();
        int nxt = it + GST - 1;
        if (nxt < NIT) load_tile(nxt % GST, nxt * GBK);
        cp_commit();

        const unsigned tAs = (unsigned)__cvta_generic_to_shared(sA + (it % GST) * TILE_F);
        const unsigned tBs = (unsigned)__cvta_generic_to_shared(sB + (it % GST) * TILE_F);
        #pragma unroll
        for (int kk = 0; kk < GBK; kk += 8) {
            const int c0 = kk >> 2;
            unsigned a[4][4];
            #pragma unroll
            for (int mf = 0; mf < 4; mf++) {
                int row = wm * 64 + mf * 16 + lhA * 8 + l7;
                unsigned saddr = tAs + ((row * 32 + (((c0 + khA) ^ l7) << 2)) << 2);
                ldsm4(a[mf], saddr);
            }
            unsigned b[2][4];
            #pragma unroll
            for (int p = 0; p < 2; p++) {
                int row = wn * 32 + p * 16 + nsB * 8 + l7;
                unsigned saddr = tBs + ((row * 32 + (((c0 + khB) ^ l7) << 2)) << 2);
                ldsm4(b[p], saddr);
            }
            #pragma unroll
            for (int p = 0; p < 2; p++)
                #pragma unroll
                for (int h = 0; h < 2; h++) {
                    const int nf = p * 2 + h;
                    #pragma unroll
                    for (int mf = 0; mf < 4; mf++)
                        mma8(acc[mf][nf], a[mf], b[p][2 * h], b[p][2 * h + 1]);
                }
        }
    }

    #pragma unroll
    for (int mf = 0; mf < 4; mf++) {
        #pragma unroll
        for (int rr = 0; rr < 2; rr++) {
            int m = m0 + wm * 64 + mf * 16 + gid + rr * 8;
            #pragma unroll
            for (int nf = 0; nf < 4; nf++) {
                int n = n0 + wn * 32 + nf * 8 + tig * 2;
                float v0 = acc[mf][nf][rr * 2 + 0] + bias[n];
                float v1 = acc[mf][nf][rr * 2 + 1] + bias[n + 1];
                if (MODE == 0) {
                    int bidx = m >> 9, s = m & 511, hh = n >> 6, d = n & 63;
                    *reinterpret_cast<float2*>(
                        &dst[(((size_t)bidx * HH + hh) * SS + s) * DK + d]) =
                        make_float2(tf2f(v0), tf2f(v1));
                } else {
                    v0 += xres[(size_t)m * DD + n];
                    v1 += xres[(size_t)m * DD + n + 1];
                    *reinterpret_cast<float2*>(&dst[(size_t)m * DD + n]) = make_float2(v0, v1);
                }
            }
        }
    }
}

// =====================================================================
// Fused attention, 512 threads. Phase 1 uses XOR-swizzled Q/K tiles
// (64-float rows, 16 chunks, low-3-bit chunk swizzle) + ldmatrix.x4.
//   phase1: 2(M)x8(N) warp grid, acc[2][8][4], 6 LDSM + 16 HMMA per kk
//   blend:  32 iters/thread, PF=8 hv ring, bit-packed masks in smem
//   phase2: softmax, 4 rows/warp
//   phase3: 4(M)x4(N) warp grid, V linear stride-72 (unchanged)
// =====================================================================
#define AST 72
#define SK_FLOATS (64 * 516)               // 33024 (scores overlay > K tile 32768)
#define VB_FLOATS (64 * AST)               // 4608
#define MASK_WORDS (64 * 16)
#define ATTN_SMEM_BYTES ((SK_FLOATS + 3 * VB_FLOATS + 2 * MASK_WORDS) * 4)  // 195584
#define PF 8

__global__ __launch_bounds__(512)
void attn_fused_kernel(const float* __restrict__ help_vals,
                       float* __restrict__ attn_out)
{
    extern __shared__ float smem[];
    float* sK = smem;                      // K tile (swizzled) / scores overlay
    float* vb0 = smem + SK_FLOATS;         // Q (swizzled), later V chunks
    float* vb1 = vb0 + VB_FLOATS;
    float* vb2 = vb1 + VB_FLOATS;
    unsigned* sMH = (unsigned*)(vb2 + VB_FLOATS);
    unsigned* sMA = sMH + MASK_WORDS;

    const int bh = blockIdx.x;
    const int b = bh >> 4;
    const int h = bh & 15;
    const int q0 = blockIdx.y * 64;
    const int tid = threadIdx.x;
    const int warp = tid >> 5, lane = tid & 31, gid = lane >> 2, tig = lane & 3;

    const int l7  = lane & 7;
    const int lhA = (lane >> 3) & 1;
    const int khA = lane >> 4;
    const int khB = (lane >> 3) & 1;
    const int nsB = lane >> 4;

    const float* vsrcb = g_v + (size_t)bh * SS * DK;

    // ---- async load Q (swizzled), K (swizzled), and bit-packed masks ----
    {
        const float* qsrc = g_q + ((size_t)bh * SS + q0) * DK;
        #pragma unroll
        for (int j = 0; j < 2; j++) {        // Q: 64 rows x 16 chunks
            int idx = tid + 512 * j;
            int r = idx >> 4, c = idx & 15;
            int sw = (c & 8) | ((c ^ (r & 7)) & 7);
            cp16(vb0 + r * 64 + (sw << 2), qsrc + r * DK + (c << 2));
        }
        const float* ksrc = g_k + (size_t)bh * SS * DK;
        #pragma unroll
        for (int j = 0; j < 16; j++) {       // K: 512 rows x 16 chunks
            int idx = tid + 512 * j;
            int r = idx >> 4, c = idx & 15;
            int sw = (c & 8) | ((c ^ (r & 7)) & 7);
            cp16(sK + r * 64 + (sw << 2), ksrc + r * DK + (c << 2));
        }
        if (tid < 256) {
            int r = tid >> 2, c = (tid & 3) << 2;
            cp16((float*)(sMH + r * 16 + c),
                 (const float*)(g_hmp + ((size_t)bh * SS + q0 + r) * 16 + c));
        } else {
            int t = tid - 256;
            int r = t >> 2, c = (t & 3) << 2;
            cp16((float*)(sMA + r * 16 + c),
                 (const float*)(g_amp + ((size_t)b * SS + q0 + r) * 16 + c));
        }
        cp_commit();
        cp_wait<0>();
        __syncthreads();
    }

    const int wm = warp & 1;    // 2 groups of 32 q-rows
    const int wn = warp >> 1;   // 8 groups of 64 key-cols

    // ---- pre-issue first hv batch (overlaps phase-1 mma) ----
    const float* hvp = help_vals + ((size_t)bh * SS + q0) * SS;
    const int base_lm = wm * 32 + gid;
    const int base_ln = wn * 64 + tig * 2;

    float2 hvb[PF];
    #pragma unroll
    for (int i = 0; i < PF; i++) {
        int lm = base_lm + ((i >> 4) << 4) + (((i >> 3) & 1) << 3);
        int ln = base_ln + ((i & 7) << 3);
        hvb[i] = __ldcs(reinterpret_cast<const float2*>(hvp + (size_t)lm * SS + ln));
    }

    // ---- phase 1: scores = Q @ K^T (ldmatrix frags) ----
    float acc[2][8][4];
    #pragma unroll
    for (int i = 0; i < 2; i++)
        #pragma unroll
        for (int j = 0; j < 8; j++)
            #pragma unroll
            for (int k = 0; k < 4; k++) acc[i][j][k] = 0.f;

    {
        const unsigned sQu = (unsigned)__cvta_generic_to_shared(vb0);
        const unsigned sKu = (unsigned)__cvta_generic_to_shared(sK);
        #pragma unroll 1
        for (int kk = 0; kk < DK; kk += 8) {
            const int c0 = kk >> 2;
            unsigned a[2][4];
            #pragma unroll
            for (int mf = 0; mf < 2; mf++) {
                int row = wm * 32 + mf * 16 + lhA * 8 + l7;
                int ch = c0 + khA;
                int sw = (ch & 8) | ((ch ^ l7) & 7);
                ldsm4(a[mf], sQu + ((row * 64 + (sw << 2)) << 2));
            }
            unsigned bfr[4][4];
            #pragma unroll
            for (int p = 0; p < 4; p++) {
                int row = wn * 64 + p * 16 + nsB * 8 + l7;
                int ch = c0 + khB;
                int sw = (ch & 8) | ((ch ^ l7) & 7);
                ldsm4(bfr[p], sKu + ((row * 64 + (sw << 2)) << 2));
            }
            #pragma unroll
            for (int p = 0; p < 4; p++)
                #pragma unroll
                for (int hh2 = 0; hh2 < 2; hh2++) {
                    const int nf = p * 2 + hh2;
                    mma8(acc[0][nf], a[0], bfr[p][2 * hh2], bfr[p][2 * hh2 + 1]);
                    mma8(acc[1][nf], a[1], bfr[p][2 * hh2], bfr[p][2 * hh2 + 1]);
                }
        }
    }
    __syncthreads();   // K/Q dead; overlay scores on sK

    // prefetch V chunks 0,1 (land during blend + softmax)
    {
        #pragma unroll
        for (int j = 0; j < 2; j++) {
            int idx = tid + 512 * j;
            int r = idx >> 4, c = (idx & 15) << 2;
            cp16(vb1 + r * AST + c, vsrcb + r * DK + c);
        }
        cp_commit();
        #pragma unroll
        for (int j = 0; j < 2; j++) {
            int idx = tid + 512 * j;
            int r = idx >> 4, c = (idx & 15) << 2;
            cp16(vb2 + r * AST + c, vsrcb + (64 + r) * DK + c);
        }
        cp_commit();
    }

    // ---- blend: scale + attn_mask + dependency blend -> sK ----
    {
        #pragma unroll
        for (int i = 0; i < 32; i++) {
            const int slot = i & (PF - 1);
            float2 hv2 = hvb[slot];
            if (i + PF < 32) {
                int j = i + PF;
                int lmp = base_lm + ((j >> 4) << 4) + (((j >> 3) & 1) << 3);
                int lnp = base_ln + ((j & 7) << 3);
                hvb[slot] = __ldcs(reinterpret_cast<const float2*>(
                    hvp + (size_t)lmp * SS + lnp));
            }
            const int mf = i >> 4, rr = (i >> 3) & 1, nf = i & 7;
            const int lm = base_lm + (mf << 4) + (rr << 3);
            const int ln = base_ln + (nf << 3);
            const unsigned wh = sMH[lm * 16 + (ln >> 5)];
            const unsigned wa = sMA[lm * 16 + (ln >> 5)];
            const int sh = ln & 31;
            float s0 = ((wa >> sh) & 1u) ? NEG_INF_F : acc[mf][nf][rr * 2 + 0] * 0.125f;
            float s1 = ((wa >> (sh + 1)) & 1u) ? NEG_INF_F : acc[mf][nf][rr * 2 + 1] * 0.125f;
            if (((wh >> sh) & 1u) && hv2.x > HTHRESH_F) s0 = 0.5f * hv2.x + 0.5f * s0;
            if (((wh >> (sh + 1)) & 1u) && hv2.y > HTHRESH_F) s1 = 0.5f * hv2.y + 0.5f * s1;
            sK[lm * 516 + ln]     = s0;
            sK[lm * 516 + ln + 1] = s1;
        }
    }
    __syncthreads();

    // ---- phase 2: softmax per row (4 rows/warp); attn via __stcs ----
    {
        float* aout = attn_out + ((size_t)bh * SS + q0) * SS;
        #pragma unroll 1
        for (int j = 0; j < 4; j++) {
            int r = warp * 4 + j;
            float* row = &sK[r * 516];
            float vals[16];
            float mx = -3e38f;
            #pragma unroll
            for (int i = 0; i < 16; i++) { vals[i] = row[lane + 32 * i]; mx = fmaxf(mx, vals[i]); }
            #pragma unroll
            for (int o = 16; o > 0; o >>= 1) mx = fmaxf(mx, __shfl_xor_sync(0xffffffffu, mx, o));
            float sum = 0.f;
            #pragma unroll
            for (int i = 0; i < 16; i++) { vals[i] = __expf(vals[i] - mx); sum += vals[i]; }
            #pragma unroll
            for (int o = 16; o > 0; o >>= 1) sum += __shfl_xor_sync(0xffffffffu, sum, o);
            float inv = 1.0f / sum;
            #pragma unroll
            for (int i = 0; i < 16; i++) {
                float p = vals[i] * inv;
                __stcs(&aout[(size_t)r * SS + lane + 32 * i], p);
                row[lane + 32 * i] = tf2f(p);
            }
        }
    }

    // ---- phase 3: ctx = P @ V, triple-buffered V chunks ----
    const int wm3 = warp & 3;   // 4 groups of 16 rows
    const int wn3 = warp >> 2;  // 4 groups of 16 d-cols
    float cacc[2][4];
    #pragma unroll
    for (int j = 0; j < 2; j++)
        #pragma unroll
        for (int k = 0; k < 4; k++) cacc[j][k] = 0.f;

    float* vbuf[3] = {vb0, vb1, vb2};
    #pragma unroll 1
    for (int ch = 0; ch < 8; ch++) {
        cp_wait<1>();
        __syncthreads();
        if (ch + 2 < 8) {
            float* dstb = vbuf[(ch + 3) % 3];
            const float* src = vsrcb + (size_t)(ch + 2) * 64 * DK;
            #pragma unroll
            for (int j = 0; j < 2; j++) {
                int idx = tid + 512 * j;
                int r = idx >> 4, c = (idx & 15) << 2;
                cp16(dstb + r * AST + c, src + r * DK + c);
            }
        }
        cp_commit();

        const float* sV = vbuf[(ch + 1) % 3];
        #pragma unroll 1
        for (int kk = 0; kk < 64; kk += 8) {
            unsigned a[4];
            int rb = wm3 * 16 + gid;
            int col = ch * 64 + kk + tig;
            a[0] = __float_as_uint(sK[rb * 516 + col]);
            a[1] = __float_as_uint(sK[(rb + 8) * 516 + col]);
            a[2] = __float_as_uint(sK[rb * 516 + col + 4]);
            a[3] = __float_as_uint(sK[(rb + 8) * 516 + col + 4]);
            #pragma unroll
            for (int nf = 0; nf < 2; nf++) {
                int nb = wn3 * 16 + nf * 8 + gid;
                unsigned bb0 = __float_as_uint(sV[(kk + tig) * AST + nb]);
                unsigned bb1 = __float_as_uint(sV[(kk + 4 + tig) * AST + nb]);
                mma8(cacc[nf], a, bb0, bb1);
            }
        }
    }

    // write tf32-rounded ctx tile -> g_ctx [m = b*S+s][h*64+d]
    #pragma unroll
    for (int rr = 0; rr < 2; rr++) {
        int s = q0 + wm3 * 16 + gid + rr * 8;
        #pragma unroll
        for (int nf = 0; nf < 2; nf++) {
            int d = wn3 * 16 + nf * 8 + tig * 2;
            *reinterpret_cast<float2*>(
                &g_ctx[((size_t)b * SS + s) * DD + h * DK + d]) =
                make_float2(tf2f(cacc[nf][rr * 2]), tf2f(cacc[nf][rr * 2 + 1]));
        }
    }
}

// =====================================================================
// LayerNorm over rows of g_res -> y output (block per row, float4)
// =====================================================================
__global__ __launch_bounds__(256)
void ln_kernel(const float* __restrict__ ln_g, const float* __restrict__ ln_b,
               float* __restrict__ y_out)
{
    __shared__ float rs[8], rq[8];
    const int r = blockIdx.x, t = threadIdx.x;
    const float4* row4 = reinterpret_cast<const float4*>(g_res + (size_t)r * DD);
    float4 v = row4[t];
    float s = v.x + v.y + v.z + v.w;
    float q = v.x * v.x + v.y * v.y + v.z * v.z + v.w * v.w;
    #pragma unroll
    for (int o = 16; o > 0; o >>= 1) {
        s += __shfl_xor_sync(0xffffffffu, s, o);
        q += __shfl_xor_sync(0xffffffffu, q, o);
    }
    if ((t & 31) == 0) { rs[t >> 5] = s; rq[t >> 5] = q; }
    __syncthreads();
    if (t < 32) {
        float ss = (t < 8) ? rs[t] : 0.f;
        float qq = (t < 8) ? rq[t] : 0.f;
        #pragma unroll
        for (int o = 4; o > 0; o >>= 1) {
            ss += __shfl_xor_sync(0xffffffffu, ss, o);
            qq += __shfl_xor_sync(0xffffffffu, qq, o);
        }
        if (t == 0) { rs[0] = ss; rq[0] = qq; }
    }
    __syncthreads();
    float mean = rs[0] * (1.0f / 1024.0f);
    float var  = rq[0] * (1.0f / 1024.0f) - mean * mean;
    float rstd = rsqrtf(var + 1e-5f);
    const float4 g4 = reinterpret_cast<const float4*>(ln_g)[t];
    const float4 b4 = reinterpret_cast<const float4*>(ln_b)[t];
    float4 o;
    o.x = (v.x - mean) * rstd * g4.x + b4.x;
    o.y = (v.y - mean) * rstd * g4.y + b4.y;
    o.z = (v.z - mean) * rstd * g4.z + b4.z;
    o.w = (v.w - mean) * rstd * g4.w + b4.w;
    reinterpret_cast<float4*>(y_out + (size_t)r * DD)[t] = o;
}

// =====================================================================
extern "C" void kernel_launch(void* const* d_in, const int* in_sizes, int n_in,
                              void* d_out, int out_size)
{
    const float* x    = (const float*)d_in[0];
    const float* Wq   = (const float*)d_in[1];
    const float* bq   = (const float*)d_in[2];
    const float* Wk   = (const float*)d_in[3];
    const float* bk   = (const float*)d_in[4];
    const float* Wv   = (const float*)d_in[5];
    const float* bv   = (const float*)d_in[6];
    const float* Wo   = (const float*)d_in[7];
    const float* bo   = (const float*)d_in[8];
    const float* ln_g = (const float*)d_in[9];
    const float* ln_b = (const float*)d_in[10];
    const float* hv   = (const float*)d_in[11];
    const int*   hm   = (const int*)d_in[12];
    const int*   am   = (const int*)d_in[13];

    float* out = (float*)d_out;
    float* y_out    = out;                          // [B,S,D]
    float* attn_out = out + (size_t)MTOT * DD;      // [B,H,S,S]

    cudaFuncSetAttribute(gemm_tf32_kernel<0>,
                         cudaFuncAttributeMaxDynamicSharedMemorySize, GEMM_SMEM_BYTES);
    cudaFuncSetAttribute(gemm_tf32_kernel<1>,
                         cudaFuncAttributeMaxDynamicSharedMemorySize, GEMM_SMEM_BYTES);
    cudaFuncSetAttribute(attn_fused_kernel,
                         cudaFuncAttributeMaxDynamicSharedMemorySize, ATTN_SMEM_BYTES);

    // 0) prep: round x; round+transpose weights; pack masks to bits
    prep_round_x<<<dim3(148), 256>>>(x);
    prep_transpose_w<<<dim3(32, 32, 4), 256>>>(Wq, Wk, Wv, Wo);
    pack_masks<<<dim3(8192, 2), 256>>>(hm, am);
    // 1) QKV projections
    gemm_tf32_kernel<0><<<dim3(32, 8, 3), 256, GEMM_SMEM_BYTES>>>(bq, bk, bv, nullptr);
    // 2) fused attention (512 threads, ldmatrix phase 1)
    attn_fused_kernel<<<dim3(BHTOT, 8), 512, ATTN_SMEM_BYTES>>>(hv, attn_out);
    // 3) out projection + bias + residual
    gemm_tf32_kernel<1><<<dim3(32, 8, 1), 256, GEMM_SMEM_BYTES>>>(bo, bo, bo, x);
    // 4) LayerNorm -> y
    ln_kernel<<<dim3(MTOT), 256>>>(ln_g, ln_b, y_out);
}

// round 17
// speedup vs baseline: 1.1275x; 1.0222x over previous
#include <cuda_runtime.h>
#include <cstdint>

#define NEG_INF_F (-1e9f)
#define HTHRESH_F (-1e8f)

// B=8, S=512, D=1024, H=16, DK=64
#define BB 8
#define SS 512
#define DD 1024
#define HH 16
#define DK 64
#define MTOT (BB*SS)          // 4096
#define BHTOT (BB*HH)         // 128

// -------- scratch (device globals; no cudaMalloc allowed) --------
__device__ float g_q[BB*HH*SS*DK];
__device__ float g_k[BB*HH*SS*DK];
__device__ float g_v[BB*HH*SS*DK];
__device__ float g_ctx[MTOT*DD];
__device__ float g_res[MTOT*DD];
__device__ float g_xr[MTOT*DD];     // tf32-rounded x
// tf32-rounded, TRANSPOSED weights [N][K] (n-major rows for ldmatrix B-frags)
__device__ float g_wqt[DD*DD];
__device__ float g_wkt[DD*DD];
__device__ float g_wvt[DD*DD];
__device__ float g_wot[DD*DD];
// bit-packed masks: 512 cols -> 16 uint32 words per row
__device__ unsigned g_hmp[BHTOT*SS*16];   // 4 MB
__device__ unsigned g_amp[BB*SS*16];      // 256 KB

// -------- helpers --------
__device__ __forceinline__ unsigned f2tf(float f) {
    unsigned u;
    asm("cvt.rna.tf32.f32 %0, %1;" : "=r"(u) : "f"(f));
    return u;
}
__device__ __forceinline__ float tf2f(float f) {
    return __uint_as_float(f2tf(f));
}
__device__ __forceinline__ void mma8(float c[4], const unsigned a[4], unsigned b0, unsigned b1) {
    asm volatile(
        "mma.sync.aligned.m16n8k8.row.col.f32.tf32.tf32.f32 "
        "{%0,%1,%2,%3}, {%4,%5,%6,%7}, {%8,%9}, {%0,%1,%2,%3};\n"
        : "+f"(c[0]), "+f"(c[1]), "+f"(c[2]), "+f"(c[3])
        : "r"(a[0]), "r"(a[1]), "r"(a[2]), "r"(a[3]), "r"(b0), "r"(b1));
}
__device__ __forceinline__ void ldsm4(unsigned r[4], unsigned saddr) {
    asm volatile("ldmatrix.sync.aligned.m8n8.x4.shared.b16 {%0,%1,%2,%3}, [%4];\n"
                 : "=r"(r[0]), "=r"(r[1]), "=r"(r[2]), "=r"(r[3]) : "r"(saddr));
}
__device__ __forceinline__ void cp16(float* smem_dst, const float* gsrc) {
    unsigned d = (unsigned)__cvta_generic_to_shared(smem_dst);
    asm volatile("cp.async.cg.shared.global [%0], [%1], 16;\n" :: "r"(d), "l"(gsrc));
}
__device__ __forceinline__ void cp_commit() {
    asm volatile("cp.async.commit_group;\n");
}
template<int N>
__device__ __forceinline__ void cp_wait() {
    asm volatile("cp.async.wait_group %0;\n" :: "n"(N));
}

// =====================================================================
// Prep kernels
// =====================================================================
__global__ __launch_bounds__(256)
void prep_round_x(const float* __restrict__ x)
{
    float4* dst = (float4*)g_xr;
    const float4* src = (const float4*)x;
    const int n4 = MTOT * DD / 4;
    for (int i = blockIdx.x * blockDim.x + threadIdx.x; i < n4;
         i += gridDim.x * blockDim.x) {
        float4 v = src[i];
        v.x = tf2f(v.x); v.y = tf2f(v.y); v.z = tf2f(v.z); v.w = tf2f(v.w);
        dst[i] = v;
    }
}
__global__ __launch_bounds__(256)
void prep_transpose_w(const float* __restrict__ Wq, const float* __restrict__ Wk,
                      const float* __restrict__ Wv, const float* __restrict__ Wo)
{
    __shared__ float t[32][33];
    const int z = blockIdx.z;
    const float* W = (z == 0) ? Wq : (z == 1 ? Wk : (z == 2 ? Wv : Wo));
    float* WT = (z == 0) ? g_wqt : (z == 1 ? g_wkt : (z == 2 ? g_wvt : g_wot));
    const int k0 = blockIdx.x * 32;
    const int n0 = blockIdx.y * 32;
    const int tx = threadIdx.x & 31, ty = threadIdx.x >> 5;
    #pragma unroll
    for (int j = 0; j < 4; j++) {
        int k = k0 + ty + j * 8;
        t[ty + j * 8][tx] = tf2f(W[(size_t)k * DD + n0 + tx]);
    }
    __syncthreads();
    #pragma unroll
    for (int j = 0; j < 4; j++) {
        int n = n0 + ty + j * 8;
        WT[(size_t)n * DD + k0 + tx] = t[tx][ty + j * 8];
    }
}
__global__ __launch_bounds__(256)
void pack_masks(const int* __restrict__ hm, const int* __restrict__ am)
{
    const int warp = threadIdx.x >> 5, lane = threadIdx.x & 31;
    const int row = blockIdx.x * 8 + warp;
    if (blockIdx.y == 0) {
        const int* src = hm + (size_t)row * SS;
        unsigned* dst = g_hmp + (size_t)row * 16;
        #pragma unroll
        for (int i = 0; i < 16; i++) {
            unsigned w = __ballot_sync(0xffffffffu, src[i * 32 + lane] != 0);
            if (lane == 0) dst[i] = w;
        }
    } else {
        if (row >= BB * SS) return;
        const int* src = am + (size_t)row * SS;
        unsigned* dst = g_amp + (size_t)row * 16;
        #pragma unroll
        for (int i = 0; i < 16; i++) {
            unsigned w = __ballot_sync(0xffffffffu, src[i * 32 + lane] != 0);
            if (lane == 0) dst[i] = w;
        }
    }
}

// =====================================================================
// GEMM: C[4096,1024] = A @ W (+bias [+residual])   (unchanged)
// =====================================================================
#define GBM 128
#define GBN 128
#define GBK 32
#define GST 3
#define TILE_F (GBM * GBK)
#define GEMM_SMEM_BYTES (GST * TILE_F * 2 * 4)   // 98304

template<int MODE>
__global__ __launch_bounds__(256, 2)
void gemm_tf32_kernel(const float* __restrict__ bias0, const float* __restrict__ bias1,
                      const float* __restrict__ bias2,
                      const float* __restrict__ xres)
{
    extern __shared__ float gsm[];
    float* sA = gsm;
    float* sB = gsm + GST * TILE_F;

    const int z = blockIdx.z;
    const float* WT   = (MODE == 1) ? g_wot : ((z == 0) ? g_wqt : (z == 1 ? g_wkt : g_wvt));
    const float* bias = (z == 0) ? bias0 : (z == 1 ? bias1 : bias2);
    const float* A    = (MODE == 0) ? g_xr : g_ctx;
    float* dst = (MODE == 0) ? ((z == 0) ? g_q : (z == 1 ? g_k : g_v)) : g_res;

    const int m0 = blockIdx.x * GBM;
    const int n0 = blockIdx.y * GBN;
    const int tid = threadIdx.x;
    const int warp = tid >> 5, lane = tid & 31, gid = lane >> 2, tig = lane & 3;
    const int wm = warp & 1, wn = warp >> 1;

    const int l7  = lane & 7;
    const int lhA = (lane >> 3) & 1;
    const int khA = lane >> 4;
    const int khB = (lane >> 3) & 1;
    const int nsB = lane >> 4;

    float acc[4][4][4];
    #pragma unroll
    for (int i = 0; i < 4; i++)
        #pragma unroll
        for (int j = 0; j < 4; j++)
            #pragma unroll
            for (int k = 0; k < 4; k++) acc[i][j][k] = 0.f;

    auto load_tile = [&](int st, int kt) {
        float* dA = sA + st * TILE_F;
        float* dB = sB + st * TILE_F;
        #pragma unroll
        for (int j = 0; j < 4; j++) {
            int idx = tid + 256 * j;
            int r = idx >> 3, c = idx & 7;
            cp16(dA + r * 32 + ((c ^ (r & 7)) << 2),
                 A + (size_t)(m0 + r) * DD + kt + (c << 2));
        }
        #pragma unroll
        for (int j = 0; j < 4; j++) {
            int idx = tid + 256 * j;
            int r = idx >> 3, c = idx & 7;
            cp16(dB + r * 32 + ((c ^ (r & 7)) << 2),
                 WT + (size_t)(n0 + r) * DD + kt + (c << 2));
        }
    };

    #pragma unroll
    for (int s = 0; s < GST - 1; s++) { load_tile(s, s * GBK); cp_commit(); }

    const int NIT = DD / GBK;
    for (int it = 0; it < NIT; it++) {
        cp_wait<GST - 2>();
        __syncthreads();
        int nxt = it + GST - 1;
        if (nxt < NIT) load_tile(nxt % GST, nxt * GBK);
        cp_commit();

        const unsigned tAs = (unsigned)__cvta_generic_to_shared(sA + (it % GST) * TILE_F);
        const unsigned tBs = (unsigned)__cvta_generic_to_shared(sB + (it % GST) * TILE_F);
        #pragma unroll
        for (int kk = 0; kk < GBK; kk += 8) {
            const int c0 = kk >> 2;
            unsigned a[4][4];
            #pragma unroll
            for (int mf = 0; mf < 4; mf++) {
                int row = wm * 64 + mf * 16 + lhA * 8 + l7;
                unsigned saddr = tAs + ((row * 32 + (((c0 + khA) ^ l7) << 2)) << 2);
                ldsm4(a[mf], saddr);
            }
            unsigned b[2][4];
            #pragma unroll
            for (int p = 0; p < 2; p++) {
                int row = wn * 32 + p * 16 + nsB * 8 + l7;
                unsigned saddr = tBs + ((row * 32 + (((c0 + khB) ^ l7) << 2)) << 2);
                ldsm4(b[p], saddr);
            }
            #pragma unroll
            for (int p = 0; p < 2; p++)
                #pragma unroll
                for (int h = 0; h < 2; h++) {
                    const int nf = p * 2 + h;
                    #pragma unroll
                    for (int mf = 0; mf < 4; mf++)
                        mma8(acc[mf][nf], a[mf], b[p][2 * h], b[p][2 * h + 1]);
                }
        }
    }

    #pragma unroll
    for (int mf = 0; mf < 4; mf++) {
        #pragma unroll
        for (int rr = 0; rr < 2; rr++) {
            int m = m0 + wm * 64 + mf * 16 + gid + rr * 8;
            #pragma unroll
            for (int nf = 0; nf < 4; nf++) {
                int n = n0 + wn * 32 + nf * 8 + tig * 2;
                float v0 = acc[mf][nf][rr * 2 + 0] + bias[n];
                float v1 = acc[mf][nf][rr * 2 + 1] + bias[n + 1];
                if (MODE == 0) {
                    int bidx = m >> 9, s = m & 511, hh = n >> 6, d = n & 63;
                    *reinterpret_cast<float2*>(
                        &dst[(((size_t)bidx * HH + hh) * SS + s) * DK + d]) =
                        make_float2(tf2f(v0), tf2f(v1));
                } else {
                    v0 += xres[(size_t)m * DD + n];
                    v1 += xres[(size_t)m * DD + n + 1];
                    *reinterpret_cast<float2*>(&dst[(size_t)m * DD + n]) = make_float2(v0, v1);
                }
            }
        }
    }
}

// =====================================================================
// Fused attention, 512 threads.
//   phase1: ldmatrix Q/K frags (swizzled tiles)
//   blend:  PF=8 hv ring + bit-packed masks in smem
//   phase2: softmax, 4 rows/warp
//   phase3: ldmatrix P-frags (stride-516 overlay is bank-conflict-free:
//           516 mod 32 = 4 => 8 rows hit banks {0,4,..,28}); V scalar
// =====================================================================
#define AST 72
#define SK_FLOATS (64 * 516)               // 33024 (scores overlay > K tile 32768)
#define VB_FLOATS (64 * AST)               // 4608
#define MASK_WORDS (64 * 16)
#define ATTN_SMEM_BYTES ((SK_FLOATS + 3 * VB_FLOATS + 2 * MASK_WORDS) * 4)  // 195584
#define PF 8

__global__ __launch_bounds__(512)
void attn_fused_kernel(const float* __restrict__ help_vals,
                       float* __restrict__ attn_out)
{
    extern __shared__ float smem[];
    float* sK = smem;                      // K tile (swizzled) / scores overlay
    float* vb0 = smem + SK_FLOATS;         // Q (swizzled), later V chunks
    float* vb1 = vb0 + VB_FLOATS;
    float* vb2 = vb1 + VB_FLOATS;
    unsigned* sMH = (unsigned*)(vb2 + VB_FLOATS);
    unsigned* sMA = sMH + MASK_WORDS;

    const int bh = blockIdx.x;
    const int b = bh >> 4;
    const int h = bh & 15;
    const int q0 = blockIdx.y * 64;
    const int tid = threadIdx.x;
    const int warp = tid >> 5, lane = tid & 31, gid = lane >> 2, tig = lane & 3;

    const int l7  = lane & 7;
    const int lhA = (lane >> 3) & 1;
    const int khA = lane >> 4;
    const int khB = (lane >> 3) & 1;
    const int nsB = lane >> 4;

    const float* vsrcb = g_v + (size_t)bh * SS * DK;

    // ---- async load Q (swizzled), K (swizzled), and bit-packed masks ----
    {
        const float* qsrc = g_q + ((size_t)bh * SS + q0) * DK;
        #pragma unroll
        for (int j = 0; j < 2; j++) {        // Q: 64 rows x 16 chunks
            int idx = tid + 512 * j;
            int r = idx >> 4, c = idx & 15;
            int sw = (c & 8) | ((c ^ (r & 7)) & 7);
            cp16(vb0 + r * 64 + (sw << 2), qsrc + r * DK + (c << 2));
        }
        const float* ksrc = g_k + (size_t)bh * SS * DK;
        #pragma unroll
        for (int j = 0; j < 16; j++) {       // K: 512 rows x 16 chunks
            int idx = tid + 512 * j;
            int r = idx >> 4, c = idx & 15;
            int sw = (c & 8) | ((c ^ (r & 7)) & 7);
            cp16(sK + r * 64 + (sw << 2), ksrc + r * DK + (c << 2));
        }
        if (tid < 256) {
            int r = tid >> 2, c = (tid & 3) << 2;
            cp16((float*)(sMH + r * 16 + c),
                 (const float*)(g_hmp + ((size_t)bh * SS + q0 + r) * 16 + c));
        } else {
            int t = tid - 256;
            int r = t >> 2, c = (t & 3) << 2;
            cp16((float*)(sMA + r * 16 + c),
                 (const float*)(g_amp + ((size_t)b * SS + q0 + r) * 16 + c));
        }
        cp_commit();
        cp_wait<0>();
        __syncthreads();
    }

    const int wm = warp & 1;    // 2 groups of 32 q-rows
    const int wn = warp >> 1;   // 8 groups of 64 key-cols

    // ---- pre-issue first hv batch (overlaps phase-1 mma) ----
    const float* hvp = help_vals + ((size_t)bh * SS + q0) * SS;
    const int base_lm = wm * 32 + gid;
    const int base_ln = wn * 64 + tig * 2;

    float2 hvb[PF];
    #pragma unroll
    for (int i = 0; i < PF; i++) {
        int lm = base_lm + ((i >> 4) << 4) + (((i >> 3) & 1) << 3);
        int ln = base_ln + ((i & 7) << 3);
        hvb[i] = __ldcs(reinterpret_cast<const float2*>(hvp + (size_t)lm * SS + ln));
    }

    // ---- phase 1: scores = Q @ K^T (ldmatrix frags) ----
    float acc[2][8][4];
    #pragma unroll
    for (int i = 0; i < 2; i++)
        #pragma unroll
        for (int j = 0; j < 8; j++)
            #pragma unroll
            for (int k = 0; k < 4; k++) acc[i][j][k] = 0.f;

    {
        const unsigned sQu = (unsigned)__cvta_generic_to_shared(vb0);
        const unsigned sKu = (unsigned)__cvta_generic_to_shared(sK);
        #pragma unroll 1
        for (int kk = 0; kk < DK; kk += 8) {
            const int c0 = kk >> 2;
            unsigned a[2][4];
            #pragma unroll
            for (int mf = 0; mf < 2; mf++) {
                int row = wm * 32 + mf * 16 + lhA * 8 + l7;
                int ch = c0 + khA;
                int sw = (ch & 8) | ((ch ^ l7) & 7);
                ldsm4(a[mf], sQu + ((row * 64 + (sw << 2)) << 2));
            }
            unsigned bfr[4][4];
            #pragma unroll
            for (int p = 0; p < 4; p++) {
                int row = wn * 64 + p * 16 + nsB * 8 + l7;
                int ch = c0 + khB;
                int sw = (ch & 8) | ((ch ^ l7) & 7);
                ldsm4(bfr[p], sKu + ((row * 64 + (sw << 2)) << 2));
            }
            #pragma unroll
            for (int p = 0; p < 4; p++)
                #pragma unroll
                for (int hh2 = 0; hh2 < 2; hh2++) {
                    const int nf = p * 2 + hh2;
                    mma8(acc[0][nf], a[0], bfr[p][2 * hh2], bfr[p][2 * hh2 + 1]);
                    mma8(acc[1][nf], a[1], bfr[p][2 * hh2], bfr[p][2 * hh2 + 1]);
                }
        }
    }
    __syncthreads();   // K/Q dead; overlay scores on sK

    // prefetch V chunks 0,1 (land during blend + softmax)
    {
        #pragma unroll
        for (int j = 0; j < 2; j++) {
            int idx = tid + 512 * j;
            int r = idx >> 4, c = (idx & 15) << 2;
            cp16(vb1 + r * AST + c, vsrcb + r * DK + c);
        }
        cp_commit();
        #pragma unroll
        for (int j = 0; j < 2; j++) {
            int idx = tid + 512 * j;
            int r = idx >> 4, c = (idx & 15) << 2;
            cp16(vb2 + r * AST + c, vsrcb + (64 + r) * DK + c);
        }
        cp_commit();
    }

    // ---- blend: scale + attn_mask + dependency blend -> sK ----
    {
        #pragma unroll
        for (int i = 0; i < 32; i++) {
            const int slot = i & (PF - 1);
            float2 hv2 = hvb[slot];
            if (i + PF < 32) {
                int j = i + PF;
                int lmp = base_lm + ((j >> 4) << 4) + (((j >> 3) & 1) << 3);
                int lnp = base_ln + ((j & 7) << 3);
                hvb[slot] = __ldcs(reinterpret_cast<const float2*>(
                    hvp + (size_t)lmp * SS + lnp));
            }
            const int mf = i >> 4, rr = (i >> 3) & 1, nf = i & 7;
            const int lm = base_lm + (mf << 4) + (rr << 3);
            const int ln = base_ln + (nf << 3);
            const unsigned wh = sMH[lm * 16 + (ln >> 5)];
            const unsigned wa = sMA[lm * 16 + (ln >> 5)];
            const int sh = ln & 31;
            float s0 = ((wa >> sh) & 1u) ? NEG_INF_F : acc[mf][nf][rr * 2 + 0] * 0.125f;
            float s1 = ((wa >> (sh + 1)) & 1u) ? NEG_INF_F : acc[mf][nf][rr * 2 + 1] * 0.125f;
            if (((wh >> sh) & 1u) && hv2.x > HTHRESH_F) s0 = 0.5f * hv2.x + 0.5f * s0;
            if (((wh >> (sh + 1)) & 1u) && hv2.y > HTHRESH_F) s1 = 0.5f * hv2.y + 0.5f * s1;
            sK[lm * 516 + ln]     = s0;
            sK[lm * 516 + ln + 1] = s1;
        }
    }
    __syncthreads();

    // ---- phase 2: softmax per row (4 rows/warp); attn via __stcs ----
    {
        float* aout = attn_out + ((size_t)bh * SS + q0) * SS;
        #pragma unroll 1
        for (int j = 0; j < 4; j++) {
            int r = warp * 4 + j;
            float* row = &sK[r * 516];
            float vals[16];
            float mx = -3e38f;
            #pragma unroll
            for (int i = 0; i < 16; i++) { vals[i] = row[lane + 32 * i]; mx = fmaxf(mx, vals[i]); }
            #pragma unroll
            for (int o = 16; o > 0; o >>= 1) mx = fmaxf(mx, __shfl_xor_sync(0xffffffffu, mx, o));
            float sum = 0.f;
            #pragma unroll
            for (int i = 0; i < 16; i++) { vals[i] = __expf(vals[i] - mx); sum += vals[i]; }
            #pragma unroll
            for (int o = 16; o > 0; o >>= 1) sum += __shfl_xor_sync(0xffffffffu, sum, o);
            float inv = 1.0f / sum;
            #pragma unroll
            for (int i = 0; i < 16; i++) {
                float p = vals[i] * inv;
                __stcs(&aout[(size_t)r * SS + lane + 32 * i], p);
                row[lane + 32 * i] = tf2f(p);
            }
        }
    }

    // ---- phase 3: ctx = P @ V, ldmatrix P-frags, triple-buffered V ----
    const int wm3 = warp & 3;   // 4 groups of 16 rows
    const int wn3 = warp >> 2;  // 4 groups of 16 d-cols
    float cacc[2][4];
    #pragma unroll
    for (int j = 0; j < 2; j++)
        #pragma unroll
        for (int k = 0; k < 4; k++) cacc[j][k] = 0.f;

    const unsigned sSu = (unsigned)__cvta_generic_to_shared(sK);
    float* vbuf[3] = {vb0, vb1, vb2};
    #pragma unroll 1
    for (int ch = 0; ch < 8; ch++) {
        cp_wait<1>();
        __syncthreads();
        if (ch + 2 < 8) {
            float* dstb = vbuf[(ch + 3) % 3];
            const float* src = vsrcb + (size_t)(ch + 2) * 64 * DK;
            #pragma unroll
            for (int j = 0; j < 2; j++) {
                int idx = tid + 512 * j;
                int r = idx >> 4, c = (idx & 15) << 2;
                cp16(dstb + r * AST + c, src + r * DK + c);
            }
        }
        cp_commit();

        const float* sV = vbuf[(ch + 1) % 3];
        #pragma unroll 1
        for (int kk = 0; kk < 64; kk += 8) {
            unsigned a[4];
            {
                int row = wm3 * 16 + lhA * 8 + l7;
                int col = ch * 64 + kk + khA * 4;
                ldsm4(a, sSu + ((row * 516 + col) << 2));
            }
            #pragma unroll
            for (int nf = 0; nf < 2; nf++) {
                int nb = wn3 * 16 + nf * 8 + gid;
                unsigned bb0 = __float_as_uint(sV[(kk + tig) * AST + nb]);
                unsigned bb1 = __float_as_uint(sV[(kk + 4 + tig) * AST + nb]);
                mma8(cacc[nf], a, bb0, bb1);
            }
        }
    }

    // write tf32-rounded ctx tile -> g_ctx [m = b*S+s][h*64+d]
    #pragma unroll
    for (int rr = 0; rr < 2; rr++) {
        int s = q0 + wm3 * 16 + gid + rr * 8;
        #pragma unroll
        for (int nf = 0; nf < 2; nf++) {
            int d = wn3 * 16 + nf * 8 + tig * 2;
            *reinterpret_cast<float2*>(
                &g_ctx[((size_t)b * SS + s) * DD + h * DK + d]) =
                make_float2(tf2f(cacc[nf][rr * 2]), tf2f(cacc[nf][rr * 2 + 1]));
        }
    }
}

// =====================================================================
// LayerNorm over rows of g_res -> y output (block per row, float4)
// =====================================================================
__global__ __launch_bounds__(256)
void ln_kernel(const float* __restrict__ ln_g, const float* __restrict__ ln_b,
               float* __restrict__ y_out)
{
    __shared__ float rs[8], rq[8];
    const int r = blockIdx.x, t = threadIdx.x;
    const float4* row4 = reinterpret_cast<const float4*>(g_res + (size_t)r * DD);
    float4 v = row4[t];
    float s = v.x + v.y + v.z + v.w;
    float q = v.x * v.x + v.y * v.y + v.z * v.z + v.w * v.w;
    #pragma unroll
    for (int o = 16; o > 0; o >>= 1) {
        s += __shfl_xor_sync(0xffffffffu, s, o);
        q += __shfl_xor_sync(0xffffffffu, q, o);
    }
    if ((t & 31) == 0) { rs[t >> 5] = s; rq[t >> 5] = q; }
    __syncthreads();
    if (t < 32) {
        float ss = (t < 8) ? rs[t] : 0.f;
        float qq = (t < 8) ? rq[t] : 0.f;
        #pragma unroll
        for (int o = 4; o > 0; o >>= 1) {
            ss += __shfl_xor_sync(0xffffffffu, ss, o);
            qq += __shfl_xor_sync(0xffffffffu, qq, o);
        }
        if (t == 0) { rs[0] = ss; rq[0] = qq; }
    }
    __syncthreads();
    float mean = rs[0] * (1.0f / 1024.0f);
    float var  = rq[0] * (1.0f / 1024.0f) - mean * mean;
    float rstd = rsqrtf(var + 1e-5f);
    const float4 g4 = reinterpret_cast<const float4*>(ln_g)[t];
    const float4 b4 = reinterpret_cast<const float4*>(ln_b)[t];
    float4 o;
    o.x = (v.x - mean) * rstd * g4.x + b4.x;
    o.y = (v.y - mean) * rstd * g4.y + b4.y;
    o.z = (v.z - mean) * rstd * g4.z + b4.z;
    o.w = (v.w - mean) * rstd * g4.w + b4.w;
    reinterpret_cast<float4*>(y_out + (size_t)r * DD)[t] = o;
}

// =====================================================================
extern "C" void kernel_launch(void* const* d_in, const int* in_sizes, int n_in,
                              void* d_out, int out_size)
{
    const float* x    = (const float*)d_in[0];
    const float* Wq   = (const float*)d_in[1];
    const float* bq   = (const float*)d_in[2];
    const float* Wk   = (const float*)d_in[3];
    const float* bk   = (const float*)d_in[4];
    const float* Wv   = (const float*)d_in[5];
    const float* bv   = (const float*)d_in[6];
    const float* Wo   = (const float*)d_in[7];
    const float* bo   = (const float*)d_in[8];
    const float* ln_g = (const float*)d_in[9];
    const float* ln_b = (const float*)d_in[10];
    const float* hv   = (const float*)d_in[11];
    const int*   hm   = (const int*)d_in[12];
    const int*   am   = (const int*)d_in[13];

    float* out = (float*)d_out;
    float* y_out    = out;                          // [B,S,D]
    float* attn_out = out + (size_t)MTOT * DD;      // [B,H,S,S]

    cudaFuncSetAttribute(gemm_tf32_kernel<0>,
                         cudaFuncAttributeMaxDynamicSharedMemorySize, GEMM_SMEM_BYTES);
    cudaFuncSetAttribute(gemm_tf32_kernel<1>,
                         cudaFuncAttributeMaxDynamicSharedMemorySize, GEMM_SMEM_BYTES);
    cudaFuncSetAttribute(attn_fused_kernel,
                         cudaFuncAttributeMaxDynamicSharedMemorySize, ATTN_SMEM_BYTES);

    // 0) prep: round x; round+transpose weights; pack masks to bits
    prep_round_x<<<dim3(148), 256>>>(x);
    prep_transpose_w<<<dim3(32, 32, 4), 256>>>(Wq, Wk, Wv, Wo);
    pack_masks<<<dim3(8192, 2), 256>>>(hm, am);
    // 1) QKV projections
    gemm_tf32_kernel<0><<<dim3(32, 8, 3), 256, GEMM_SMEM_BYTES>>>(bq, bk, bv, nullptr);
    // 2) fused attention (512 threads, ldmatrix phases 1+3)
    attn_fused_kernel<<<dim3(BHTOT, 8), 512, ATTN_SMEM_BYTES>>>(hv, attn_out);
    // 3) out projection + bias + residual
    gemm_tf32_kernel<1><<<dim3(32, 8, 1), 256, GEMM_SMEM_BYTES>>>(bo, bo, bo, x);
    // 4) LayerNorm -> y
    ln_kernel<<<dim3(MTOT), 256>>>(ln_g, ln_b, y_out);
}